// round 1
// baseline (speedup 1.0000x reference)
#include <cuda_runtime.h>
#include <math.h>

// ---------------------------------------------------------------------------
// Problem constants (GRID is fixed in the dataset: [[1,48,48],[1,32,64],[2,24,40]])
// ---------------------------------------------------------------------------
#define NTOK    6272
#define DMODEL  1152
#define HEADS   16
#define HDIM    72
#define IDIM    4304
#define DOUT    2048
#define MROWS   1568          // NTOK / 4
#define MD      4608          // DMODEL * 4
#define QKVW    3456          // 3*DMODEL

static const int h_seg_start[4] = {0, 2304, 4352, 5312};
static const int h_seg_len[4]   = {2304, 2048, 960, 960};

// ---------------------------------------------------------------------------
// Scratch (static device globals; no allocation anywhere)
// ---------------------------------------------------------------------------
__device__ float g_x    [NTOK * DMODEL];          // residual stream
__device__ float g_h    [NTOK * DMODEL];          // LN output
__device__ float g_qkv  [NTOK * QKVW];            // q|k|v
__device__ float g_attn [NTOK * DMODEL];          // attention output
__device__ float g_mlp  [NTOK * IDIM];            // MLP hidden / merger hidden
__device__ float g_logits[(size_t)HEADS * 2304 * 2304]; // largest segment
__device__ float g_cos  [NTOK * 36];
__device__ float g_sin  [NTOK * 36];

// ---------------------------------------------------------------------------
// Token -> (row, col, image h, image w) mapping (matches reference ordering:
// (t, hb, wb, mi, mj) with M=2)
// ---------------------------------------------------------------------------
__device__ __forceinline__ void token_pos(int n, int& row, int& col, int& ih, int& iw)
{
    int local, h, w;
    if (n < 2304)      { local = n;          h = 48; w = 48; }
    else if (n < 4352) { local = n - 2304;   h = 32; w = 64; }
    else               { local = n - 4352;   h = 24; w = 40; }
    int rem = local % (h * w);          // position within one t-frame
    int wb_cnt = w >> 1;
    int blk = rem >> 2, within = rem & 3;
    int hb = blk / wb_cnt, wb = blk % wb_cnt;
    row = hb * 2 + (within >> 1);
    col = wb * 2 + (within & 1);
    ih = h; iw = w;
}

// ---------------------------------------------------------------------------
// RoPE cos/sin tables (36 unique values per token; dims [36,72) duplicate [0,36))
// ---------------------------------------------------------------------------
__global__ void cossin_kernel()
{
    int idx = blockIdx.x * blockDim.x + threadIdx.x;
    if (idx >= NTOK * 36) return;
    int n = idx / 36, d = idx % 36;
    int row, col, ih, iw;
    token_pos(n, row, col, ih, iw);
    int j = (d < 18) ? d : d - 18;
    double p = (d < 18) ? (double)row : (double)col;
    double inv = 1.0 / pow(10000.0, (2.0 * (double)j) / 36.0);
    double ang = p * inv;
    g_cos[idx] = (float)cos(ang);
    g_sin[idx] = (float)sin(ang);
}

// ---------------------------------------------------------------------------
// Bilinear positional-embedding add:  x[n,:] += bilerp(pos_table)
// ---------------------------------------------------------------------------
__global__ void posadd_kernel(const float* __restrict__ pos_table)
{
    int n = blockIdx.x;
    int row, col, ih, iw;
    token_pos(n, row, col, ih, iw);
    double hi = 47.0 * (double)row / (double)(ih - 1);
    double wi = 47.0 * (double)col / (double)(iw - 1);
    int hf = (int)floor(hi), wf = (int)floor(wi);
    float dh = (float)(hi - (double)hf), dw = (float)(wi - (double)wf);
    int hc = min(hf + 1, 47), wc = min(wf + 1, 47);
    float w00 = (1.f - dh) * (1.f - dw);
    float w01 = (1.f - dh) * dw;
    float w10 = dh * (1.f - dw);
    float w11 = dh * dw;
    const float* p00 = pos_table + (size_t)(hf * 48 + wf) * DMODEL;
    const float* p01 = pos_table + (size_t)(hf * 48 + wc) * DMODEL;
    const float* p10 = pos_table + (size_t)(hc * 48 + wf) * DMODEL;
    const float* p11 = pos_table + (size_t)(hc * 48 + wc) * DMODEL;
    float* xr = g_x + (size_t)n * DMODEL;
    for (int d = threadIdx.x; d < DMODEL; d += blockDim.x)
        xr[d] += p00[d] * w00 + p01[d] * w01 + p10[d] * w10 + p11[d] * w11;
}

// ---------------------------------------------------------------------------
// Reductions
// ---------------------------------------------------------------------------
__device__ __forceinline__ float warp_sum(float v)
{
#pragma unroll
    for (int o = 16; o > 0; o >>= 1) v += __shfl_xor_sync(0xffffffffu, v, o);
    return v;
}
__device__ __forceinline__ float warp_max(float v)
{
#pragma unroll
    for (int o = 16; o > 0; o >>= 1) v = fmaxf(v, __shfl_xor_sync(0xffffffffu, v, o));
    return v;
}

// ---------------------------------------------------------------------------
// LayerNorm over D=1152.  288 threads/block, 4 elems/thread.
// ---------------------------------------------------------------------------
__global__ void ln_kernel(const float* __restrict__ in, float* __restrict__ out,
                          const float* __restrict__ s, const float* __restrict__ b)
{
    __shared__ float sh[9];
    __shared__ float stat[2];
    int n = blockIdx.x;
    const float* xr = in + (size_t)n * DMODEL;
    int t = threadIdx.x, wid = t >> 5, lane = t & 31;

    float vals[4];
    float lsum = 0.f;
#pragma unroll
    for (int i = 0; i < 4; i++) { vals[i] = xr[t + i * 288]; lsum += vals[i]; }
    float ws = warp_sum(lsum);
    if (lane == 0) sh[wid] = ws;
    __syncthreads();
    if (t == 0) {
        float tot = 0.f;
#pragma unroll
        for (int i = 0; i < 9; i++) tot += sh[i];
        stat[0] = tot * (1.0f / DMODEL);
    }
    __syncthreads();
    float mu = stat[0];
    float lvar = 0.f;
#pragma unroll
    for (int i = 0; i < 4; i++) { float d = vals[i] - mu; lvar += d * d; }
    ws = warp_sum(lvar);
    __syncthreads();                 // protect sh reuse
    if (lane == 0) sh[wid] = ws;
    __syncthreads();
    if (t == 0) {
        float tot = 0.f;
#pragma unroll
        for (int i = 0; i < 9; i++) tot += sh[i];
        stat[1] = rsqrtf(tot * (1.0f / DMODEL) + 1e-6f);
    }
    __syncthreads();
    float r = stat[1];
    float* orow = out + (size_t)n * DMODEL;
#pragma unroll
    for (int i = 0; i < 4; i++) {
        int d = t + i * 288;
        orow[d] = (vals[i] - mu) * r * s[d] + b[d];
    }
}

// ---------------------------------------------------------------------------
// RoPE in-place on q and k inside g_qkv.  Block per token, 576 threads =
// 16 heads * 36 rotation pairs.
// ---------------------------------------------------------------------------
__global__ void rope_kernel()
{
    int n = blockIdx.x;
    int t = threadIdx.x;
    int h = t / 36, d = t % 36;
    float c = g_cos[n * 36 + d];
    float s = g_sin[n * 36 + d];
    float* q = g_qkv + (size_t)n * QKVW + h * HDIM;
    float* k = q + DMODEL;
    float q0 = q[d], q1 = q[d + 36];
    q[d]      = q0 * c - q1 * s;
    q[d + 36] = q1 * c + q0 * s;
    float k0 = k[d], k1 = k[d + 36];
    k[d]      = k0 * c - k1 * s;
    k[d + 36] = k1 * c + k0 * s;
}

// ---------------------------------------------------------------------------
// Row softmax (fp32).  One block (256 threads) per (head,row); rows contiguous.
// ---------------------------------------------------------------------------
__global__ void softmax_kernel(float* __restrict__ logits, int S)
{
    float* p = logits + (size_t)blockIdx.x * S;
    __shared__ float sh[8];
    __shared__ float stat;
    int t = threadIdx.x, wid = t >> 5, lane = t & 31;

    float m = -1e30f;
    for (int j = t; j < S; j += 256) m = fmaxf(m, p[j]);
    m = warp_max(m);
    if (lane == 0) sh[wid] = m;
    __syncthreads();
    if (t == 0) {
        float mm = sh[0];
#pragma unroll
        for (int i = 1; i < 8; i++) mm = fmaxf(mm, sh[i]);
        stat = mm;
    }
    __syncthreads();
    m = stat;
    float sum = 0.f;
    for (int j = t; j < S; j += 256) {
        float e = expf(p[j] - m);
        p[j] = e;
        sum += e;
    }
    sum = warp_sum(sum);
    __syncthreads();
    if (lane == 0) sh[wid] = sum;
    __syncthreads();
    if (t == 0) {
        float tot = 0.f;
#pragma unroll
        for (int i = 0; i < 8; i++) tot += sh[i];
        stat = 1.0f / tot;
    }
    __syncthreads();
    float inv = stat;
    for (int j = t; j < S; j += 256) p[j] *= inv;
}

// ---------------------------------------------------------------------------
// Generic batched SGEMM.  C[z] = epilogue(alpha * A[z] @ op(B[z]))
//   TRANSB=false: B is [K,N] row-major (ldb).  TRANSB=true: B is [N,K] (ldb).
//   128x128 block tile, BK=8, 8x8 per thread, 256 threads.
//   Requires Kd % 8 == 0 and all leading strides % 4 == 0 (holds here).
// Epilogues: 0=store(alpha*acc)  1=+bias  2=+bias,gelu  3=+bias,+residual
// ---------------------------------------------------------------------------
#define EPI_NONE      0
#define EPI_BIAS      1
#define EPI_BIAS_GELU 2
#define EPI_BIAS_RES  3

__device__ __forceinline__ float gelu_tanh(float x)
{
    float x3 = x * x * x;
    return 0.5f * x * (1.f + tanhf(0.7978845608028654f * (x + 0.044715f * x3)));
}

template<bool TRANSB, int EPI>
__global__ void __launch_bounds__(256)
gemm_kernel(const float* __restrict__ A, int lda, long long sA,
            const float* __restrict__ B, int ldb, long long sB,
            float* __restrict__ C, int ldc, long long sC,
            const float* __restrict__ bias,
            const float* __restrict__ Res, int ldr,
            int Md, int Nd, int Kd, float alpha)
{
    A += (long long)blockIdx.z * sA;
    B += (long long)blockIdx.z * sB;
    C += (long long)blockIdx.z * sC;

    __shared__ float As[8][128];
    __shared__ float Bs[8][128];

    int tid = threadIdx.x;
    int brow = blockIdx.y * 128;
    int bcol = blockIdx.x * 128;
    int tx = tid & 15, ty = tid >> 4;

    float acc[8][8];
#pragma unroll
    for (int i = 0; i < 8; i++)
#pragma unroll
        for (int j = 0; j < 8; j++) acc[i][j] = 0.f;

    int a_row = tid >> 1;
    int a_k4  = (tid & 1) * 4;
    int b_k   = tid >> 5;
    int b_n4  = (tid & 31) * 4;

    for (int k0 = 0; k0 < Kd; k0 += 8) {
        { // A tile -> As[k][m] (transposed store)
            int gr = brow + a_row;
            float4 v = make_float4(0.f, 0.f, 0.f, 0.f);
            if (gr < Md)
                v = *reinterpret_cast<const float4*>(A + (long long)gr * lda + k0 + a_k4);
            As[a_k4 + 0][a_row] = v.x;
            As[a_k4 + 1][a_row] = v.y;
            As[a_k4 + 2][a_row] = v.z;
            As[a_k4 + 3][a_row] = v.w;
        }
        if (!TRANSB) {
            int gn = bcol + b_n4;
            float4 v = make_float4(0.f, 0.f, 0.f, 0.f);
            if (gn < Nd)
                v = *reinterpret_cast<const float4*>(B + (long long)(k0 + b_k) * ldb + gn);
            *reinterpret_cast<float4*>(&Bs[b_k][b_n4]) = v;
        } else {
            int bn  = tid >> 1;
            int kk  = (tid & 1) * 4;
            int gn  = bcol + bn;
            float4 v = make_float4(0.f, 0.f, 0.f, 0.f);
            if (gn < Nd)
                v = *reinterpret_cast<const float4*>(B + (long long)gn * ldb + k0 + kk);
            Bs[kk + 0][bn] = v.x;
            Bs[kk + 1][bn] = v.y;
            Bs[kk + 2][bn] = v.z;
            Bs[kk + 3][bn] = v.w;
        }
        __syncthreads();

#pragma unroll
        for (int k = 0; k < 8; k++) {
            float a[8], b[8];
#pragma unroll
            for (int i = 0; i < 8; i++) a[i] = As[k][ty * 8 + i];
#pragma unroll
            for (int j = 0; j < 8; j++) b[j] = Bs[k][tx * 8 + j];
#pragma unroll
            for (int i = 0; i < 8; i++)
#pragma unroll
                for (int j = 0; j < 8; j++)
                    acc[i][j] = fmaf(a[i], b[j], acc[i][j]);
        }
        __syncthreads();
    }

#pragma unroll
    for (int i = 0; i < 8; i++) {
        int r = brow + ty * 8 + i;
        if (r >= Md) continue;
#pragma unroll
        for (int j = 0; j < 8; j++) {
            int c = bcol + tx * 8 + j;
            if (c >= Nd) continue;
            float v = acc[i][j] * alpha;
            if (EPI >= EPI_BIAS)      v += bias[c];
            if (EPI == EPI_BIAS_GELU) v = gelu_tanh(v);
            if (EPI == EPI_BIAS_RES)  v += Res[(long long)r * ldr + c];
            C[(long long)r * ldc + c] = v;
        }
    }
}

// ---------------------------------------------------------------------------
// Host launcher
// ---------------------------------------------------------------------------
#define SYM(p, s) do { void* _t; cudaGetSymbolAddress(&_t, s); p = (float*)_t; } while (0)

static inline dim3 ggrid(int Md, int Nd, int z) {
    return dim3((Nd + 127) / 128, (Md + 127) / 128, z);
}

extern "C" void kernel_launch(void* const* d_in, const int* in_sizes, int n_in,
                              void* d_out, int out_size)
{
    (void)in_sizes; (void)n_in; (void)out_size;
    const float* pixel    = (const float*)d_in[0];
    const float* patch_w  = (const float*)d_in[2];
    const float* patch_b  = (const float*)d_in[3];
    const float* pos_tab  = (const float*)d_in[4];
    const float* ln1_s    = (const float*)d_in[5];
    const float* ln1_b    = (const float*)d_in[6];
    const float* qkv_w    = (const float*)d_in[7];
    const float* qkv_b    = (const float*)d_in[8];
    const float* proj_w   = (const float*)d_in[9];
    const float* proj_b   = (const float*)d_in[10];
    const float* ln2_s    = (const float*)d_in[11];
    const float* ln2_b    = (const float*)d_in[12];
    const float* fc1_w    = (const float*)d_in[13];
    const float* fc1_b    = (const float*)d_in[14];
    const float* fc2_w    = (const float*)d_in[15];
    const float* fc2_b    = (const float*)d_in[16];
    const float* m_ln_s   = (const float*)d_in[17];
    const float* m_ln_b   = (const float*)d_in[18];
    const float* m_fc1_w  = (const float*)d_in[19];
    const float* m_fc1_b  = (const float*)d_in[20];
    const float* m_fc2_w  = (const float*)d_in[21];
    const float* m_fc2_b  = (const float*)d_in[22];
    float* out = (float*)d_out;

    float *x, *h, *qkv, *attn, *mlp, *logits;
    SYM(x, g_x); SYM(h, g_h); SYM(qkv, g_qkv); SYM(attn, g_attn);
    SYM(mlp, g_mlp); SYM(logits, g_logits);

    const float scale = 0.11785113019775793f;  // 72^-0.5

    // RoPE tables
    cossin_kernel<<<(NTOK * 36 + 255) / 256, 256>>>();

    // Patch embed: x = pixel @ patch_w + patch_b
    gemm_kernel<false, EPI_BIAS><<<ggrid(NTOK, DMODEL, 1), 256>>>(
        pixel, 1536, 0, patch_w, DMODEL, 0, x, DMODEL, 0,
        patch_b, nullptr, 0, NTOK, DMODEL, 1536, 1.0f);

    // x += pos embeds
    posadd_kernel<<<NTOK, 288>>>(pos_tab);

    for (int l = 0; l < 2; l++) {
        const float* l1s = ln1_s + l * DMODEL;
        const float* l1b = ln1_b + l * DMODEL;
        const float* qw  = qkv_w + (size_t)l * DMODEL * QKVW;
        const float* qb  = qkv_b + (size_t)l * QKVW;
        const float* pw  = proj_w + (size_t)l * DMODEL * DMODEL;
        const float* pb  = proj_b + (size_t)l * DMODEL;
        const float* l2s = ln2_s + l * DMODEL;
        const float* l2b = ln2_b + l * DMODEL;
        const float* f1w = fc1_w + (size_t)l * DMODEL * IDIM;
        const float* f1b = fc1_b + (size_t)l * IDIM;
        const float* f2w = fc2_w + (size_t)l * IDIM * DMODEL;
        const float* f2b = fc2_b + (size_t)l * DMODEL;

        ln_kernel<<<NTOK, 288>>>(x, h, l1s, l1b);

        gemm_kernel<false, EPI_BIAS><<<ggrid(NTOK, QKVW, 1), 256>>>(
            h, DMODEL, 0, qw, QKVW, 0, qkv, QKVW, 0,
            qb, nullptr, 0, NTOK, QKVW, DMODEL, 1.0f);

        rope_kernel<<<NTOK, 576>>>();

        for (int s = 0; s < 4; s++) {
            int st = h_seg_start[s], S = h_seg_len[s];
            const float* qp = qkv + (size_t)st * QKVW;
            const float* kp = qp + DMODEL;
            const float* vp = qp + 2 * DMODEL;
            // logits[h] = scale * q @ k^T
            gemm_kernel<true, EPI_NONE><<<ggrid(S, S, HEADS), 256>>>(
                qp, QKVW, HDIM, kp, QKVW, HDIM,
                logits, S, (long long)S * S,
                nullptr, nullptr, 0, S, S, HDIM, scale);
            // softmax rows
            softmax_kernel<<<HEADS * S, 256>>>(logits, S);
            // attn = P @ v
            gemm_kernel<false, EPI_NONE><<<ggrid(S, HDIM, HEADS), 256>>>(
                logits, S, (long long)S * S, vp, QKVW, HDIM,
                attn + (size_t)st * DMODEL, DMODEL, HDIM,
                nullptr, nullptr, 0, S, HDIM, S, 1.0f);
        }

        // x = x + attn @ proj_w + proj_b
        gemm_kernel<false, EPI_BIAS_RES><<<ggrid(NTOK, DMODEL, 1), 256>>>(
            attn, DMODEL, 0, pw, DMODEL, 0, x, DMODEL, 0,
            pb, x, DMODEL, NTOK, DMODEL, DMODEL, 1.0f);

        ln_kernel<<<NTOK, 288>>>(x, h, l2s, l2b);

        // mlp = gelu(h @ fc1 + b1)
        gemm_kernel<false, EPI_BIAS_GELU><<<ggrid(NTOK, IDIM, 1), 256>>>(
            h, DMODEL, 0, f1w, IDIM, 0, mlp, IDIM, 0,
            f1b, nullptr, 0, NTOK, IDIM, DMODEL, 1.0f);

        // x = x + mlp @ fc2 + b2
        gemm_kernel<false, EPI_BIAS_RES><<<ggrid(NTOK, DMODEL, 1), 256>>>(
            mlp, IDIM, 0, f2w, DMODEL, 0, x, DMODEL, 0,
            f2b, x, DMODEL, NTOK, DMODEL, IDIM, 1.0f);
    }

    // merger
    ln_kernel<<<NTOK, 288>>>(x, h, m_ln_s, m_ln_b);     // h viewed as [1568,4608]

    gemm_kernel<false, EPI_BIAS_GELU><<<ggrid(MROWS, MD, 1), 256>>>(
        h, MD, 0, m_fc1_w, MD, 0, mlp, MD, 0,
        m_fc1_b, nullptr, 0, MROWS, MD, MD, 1.0f);

    gemm_kernel<false, EPI_BIAS><<<ggrid(MROWS, DOUT, 1), 256>>>(
        mlp, MD, 0, m_fc2_w, DOUT, 0, out, DOUT, 0,
        m_fc2_b, nullptr, 0, MROWS, DOUT, MD, 1.0f);
}

// round 2
// speedup vs baseline: 2.2645x; 2.2645x over previous
#include <cuda_runtime.h>
#include <math.h>
#include <stdint.h>

// ---------------------------------------------------------------------------
// Problem constants (GRID fixed: [[1,48,48],[1,32,64],[2,24,40]])
// ---------------------------------------------------------------------------
#define NTOK    6272
#define DMODEL  1152
#define HEADS   16
#define HDIM    72
#define IDIM    4304
#define DOUT    2048
#define MROWS   1568
#define MD      4608
#define QKVW    3456

static const int h_seg_start[4] = {0, 2304, 4352, 5312};
static const int h_seg_len[4]   = {2304, 2048, 960, 960};

// ---------------------------------------------------------------------------
// Scratch
// ---------------------------------------------------------------------------
__device__ float g_x    [NTOK * DMODEL];
__device__ float g_h    [NTOK * DMODEL];
__device__ float g_qkv  [NTOK * QKVW];
__device__ float g_attn [NTOK * DMODEL];
__device__ float g_mlp  [NTOK * IDIM];
__device__ float g_logits[(size_t)HEADS * 2304 * 2304];
__device__ float g_cos  [NTOK * 36];
__device__ float g_sin  [NTOK * 36];

// ---------------------------------------------------------------------------
__device__ __forceinline__ void token_pos(int n, int& row, int& col, int& ih, int& iw)
{
    int local, h, w;
    if (n < 2304)      { local = n;          h = 48; w = 48; }
    else if (n < 4352) { local = n - 2304;   h = 32; w = 64; }
    else               { local = n - 4352;   h = 24; w = 40; }
    int rem = local % (h * w);
    int wb_cnt = w >> 1;
    int blk = rem >> 2, within = rem & 3;
    int hb = blk / wb_cnt, wb = blk % wb_cnt;
    row = hb * 2 + (within >> 1);
    col = wb * 2 + (within & 1);
    ih = h; iw = w;
}

__global__ void cossin_kernel()
{
    int idx = blockIdx.x * blockDim.x + threadIdx.x;
    if (idx >= NTOK * 36) return;
    int n = idx / 36, d = idx % 36;
    int row, col, ih, iw;
    token_pos(n, row, col, ih, iw);
    int j = (d < 18) ? d : d - 18;
    double p = (d < 18) ? (double)row : (double)col;
    double inv = 1.0 / pow(10000.0, (2.0 * (double)j) / 36.0);
    double ang = p * inv;
    g_cos[idx] = (float)cos(ang);
    g_sin[idx] = (float)sin(ang);
}

__global__ void posadd_kernel(const float* __restrict__ pos_table)
{
    int n = blockIdx.x;
    int row, col, ih, iw;
    token_pos(n, row, col, ih, iw);
    double hi = 47.0 * (double)row / (double)(ih - 1);
    double wi = 47.0 * (double)col / (double)(iw - 1);
    int hf = (int)floor(hi), wf = (int)floor(wi);
    float dh = (float)(hi - (double)hf), dw = (float)(wi - (double)wf);
    int hc = min(hf + 1, 47), wc = min(wf + 1, 47);
    float w00 = (1.f - dh) * (1.f - dw);
    float w01 = (1.f - dh) * dw;
    float w10 = dh * (1.f - dw);
    float w11 = dh * dw;
    const float* p00 = pos_table + (size_t)(hf * 48 + wf) * DMODEL;
    const float* p01 = pos_table + (size_t)(hf * 48 + wc) * DMODEL;
    const float* p10 = pos_table + (size_t)(hc * 48 + wf) * DMODEL;
    const float* p11 = pos_table + (size_t)(hc * 48 + wc) * DMODEL;
    float* xr = g_x + (size_t)n * DMODEL;
    for (int d = threadIdx.x; d < DMODEL; d += blockDim.x)
        xr[d] += p00[d] * w00 + p01[d] * w01 + p10[d] * w10 + p11[d] * w11;
}

__device__ __forceinline__ float warp_sum(float v)
{
#pragma unroll
    for (int o = 16; o > 0; o >>= 1) v += __shfl_xor_sync(0xffffffffu, v, o);
    return v;
}
__device__ __forceinline__ float warp_max(float v)
{
#pragma unroll
    for (int o = 16; o > 0; o >>= 1) v = fmaxf(v, __shfl_xor_sync(0xffffffffu, v, o));
    return v;
}

__global__ void ln_kernel(const float* __restrict__ in, float* __restrict__ out,
                          const float* __restrict__ s, const float* __restrict__ b)
{
    __shared__ float sh[9];
    __shared__ float stat[2];
    int n = blockIdx.x;
    const float* xr = in + (size_t)n * DMODEL;
    int t = threadIdx.x, wid = t >> 5, lane = t & 31;

    float vals[4];
    float lsum = 0.f;
#pragma unroll
    for (int i = 0; i < 4; i++) { vals[i] = xr[t + i * 288]; lsum += vals[i]; }
    float ws = warp_sum(lsum);
    if (lane == 0) sh[wid] = ws;
    __syncthreads();
    if (t == 0) {
        float tot = 0.f;
#pragma unroll
        for (int i = 0; i < 9; i++) tot += sh[i];
        stat[0] = tot * (1.0f / DMODEL);
    }
    __syncthreads();
    float mu = stat[0];
    float lvar = 0.f;
#pragma unroll
    for (int i = 0; i < 4; i++) { float d = vals[i] - mu; lvar += d * d; }
    ws = warp_sum(lvar);
    __syncthreads();
    if (lane == 0) sh[wid] = ws;
    __syncthreads();
    if (t == 0) {
        float tot = 0.f;
#pragma unroll
        for (int i = 0; i < 9; i++) tot += sh[i];
        stat[1] = rsqrtf(tot * (1.0f / DMODEL) + 1e-6f);
    }
    __syncthreads();
    float r = stat[1];
    float* orow = out + (size_t)n * DMODEL;
#pragma unroll
    for (int i = 0; i < 4; i++) {
        int d = t + i * 288;
        orow[d] = (vals[i] - mu) * r * s[d] + b[d];
    }
}

__global__ void rope_kernel()
{
    int n = blockIdx.x;
    int t = threadIdx.x;
    int h = t / 36, d = t % 36;
    float c = g_cos[n * 36 + d];
    float s = g_sin[n * 36 + d];
    float* q = g_qkv + (size_t)n * QKVW + h * HDIM;
    float* k = q + DMODEL;
    float q0 = q[d], q1 = q[d + 36];
    q[d]      = q0 * c - q1 * s;
    q[d + 36] = q1 * c + q0 * s;
    float k0 = k[d], k1 = k[d + 36];
    k[d]      = k0 * c - k1 * s;
    k[d + 36] = k1 * c + k0 * s;
}

__global__ void softmax_kernel(float* __restrict__ logits, int S)
{
    float* p = logits + (size_t)blockIdx.x * S;
    __shared__ float sh[8];
    __shared__ float stat;
    int t = threadIdx.x, wid = t >> 5, lane = t & 31;

    float m = -1e30f;
    for (int j = t; j < S; j += 256) m = fmaxf(m, p[j]);
    m = warp_max(m);
    if (lane == 0) sh[wid] = m;
    __syncthreads();
    if (t == 0) {
        float mm = sh[0];
#pragma unroll
        for (int i = 1; i < 8; i++) mm = fmaxf(mm, sh[i]);
        stat = mm;
    }
    __syncthreads();
    m = stat;
    float sum = 0.f;
    for (int j = t; j < S; j += 256) {
        float e = expf(p[j] - m);
        p[j] = e;
        sum += e;
    }
    sum = warp_sum(sum);
    __syncthreads();
    if (lane == 0) sh[wid] = sum;
    __syncthreads();
    if (t == 0) {
        float tot = 0.f;
#pragma unroll
        for (int i = 0; i < 8; i++) tot += sh[i];
        stat = 1.0f / tot;
    }
    __syncthreads();
    float inv = stat;
    for (int j = t; j < S; j += 256) p[j] *= inv;
}

// ---------------------------------------------------------------------------
// TF32 tensor-core batched GEMM.  C[z] = epilogue(alpha * A[z] @ op(B[z]))
//   Block tile 128x128, BK=16, 256 threads (8 warps, 2x4 warp grid, 64x32
//   each).  Fragments via mma.sync.aligned.m16n8k8 tf32, fp32 accumulate.
//   Requires Kd % 8 == 0, Nd % 4 == 0, leading strides % 4 == 0.
// ---------------------------------------------------------------------------
#define EPI_NONE      0
#define EPI_BIAS      1
#define EPI_BIAS_GELU 2
#define EPI_BIAS_RES  3

__device__ __forceinline__ float gelu_tanh(float x)
{
    float x3 = x * x * x;
    return 0.5f * x * (1.f + tanhf(0.7978845608028654f * (x + 0.044715f * x3)));
}

__device__ __forceinline__ uint32_t f2tf32(float x)
{
    uint32_t r;
    asm("cvt.rna.tf32.f32 %0, %1;" : "=r"(r) : "f"(x));
    return r;
}

__device__ __forceinline__ void mma_tf32(float c[4],
                                         uint32_t a0, uint32_t a1, uint32_t a2, uint32_t a3,
                                         uint32_t b0, uint32_t b1)
{
    asm volatile(
        "mma.sync.aligned.m16n8k8.row.col.f32.tf32.tf32.f32 "
        "{%0,%1,%2,%3}, {%4,%5,%6,%7}, {%8,%9}, {%0,%1,%2,%3};\n"
        : "+f"(c[0]), "+f"(c[1]), "+f"(c[2]), "+f"(c[3])
        : "r"(a0), "r"(a1), "r"(a2), "r"(a3), "r"(b0), "r"(b1));
}

#define BKD 16
#define SMPAD 4      // row stride 132 floats -> conflict-free fragment reads

template<bool TRANSB, int EPI>
__global__ void __launch_bounds__(256)
gemm_tc(const float* __restrict__ A, int lda, long long sA,
        const float* __restrict__ B, int ldb, long long sB,
        float* __restrict__ C, int ldc, long long sC,
        const float* __restrict__ bias,
        const float* __restrict__ Res, int ldr,
        int Md, int Nd, int Kd, float alpha)
{
    A += (long long)blockIdx.z * sA;
    B += (long long)blockIdx.z * sB;
    C += (long long)blockIdx.z * sC;

    __shared__ uint32_t As[BKD][128 + SMPAD];
    __shared__ uint32_t Bs[BKD][128 + SMPAD];

    const int tid  = threadIdx.x;
    const int brow = blockIdx.y * 128;
    const int bcol = blockIdx.x * 128;
    const int w    = tid >> 5;
    const int lane = tid & 31;
    const int g    = lane >> 2;     // 0..7
    const int q    = lane & 3;      // 0..3
    const int wm   = w & 1;         // 2 warps in M
    const int wn   = w >> 1;        // 4 warps in N

    float acc[4][4][4];
#pragma unroll
    for (int i = 0; i < 4; i++)
#pragma unroll
        for (int j = 0; j < 4; j++)
#pragma unroll
            for (int r = 0; r < 4; r++) acc[i][j][r] = 0.f;

    for (int k0 = 0; k0 < Kd; k0 += BKD) {
        // ---- A tile: [128 m][16 k] -> As[k][m]
#pragma unroll
        for (int si = 0; si < 2; si++) {
            int s  = tid + si * 256;          // 0..511
            int m  = s >> 2;                  // 0..127
            int k4 = (s & 3) * 4;
            int gr = brow + m;
            float4 v = make_float4(0.f, 0.f, 0.f, 0.f);
            if (gr < Md && (k0 + k4) < Kd)
                v = *reinterpret_cast<const float4*>(A + (long long)gr * lda + k0 + k4);
            As[k4 + 0][m] = f2tf32(v.x);
            As[k4 + 1][m] = f2tf32(v.y);
            As[k4 + 2][m] = f2tf32(v.z);
            As[k4 + 3][m] = f2tf32(v.w);
        }
        // ---- B tile -> Bs[k][n]
        if (!TRANSB) {
#pragma unroll
            for (int si = 0; si < 2; si++) {
                int s  = tid + si * 256;
                int k  = s >> 5;              // 0..15
                int n4 = (s & 31) * 4;
                int gn = bcol + n4;
                float4 v = make_float4(0.f, 0.f, 0.f, 0.f);
                if (gn < Nd && (k0 + k) < Kd)
                    v = *reinterpret_cast<const float4*>(B + (long long)(k0 + k) * ldb + gn);
                Bs[k][n4 + 0] = f2tf32(v.x);
                Bs[k][n4 + 1] = f2tf32(v.y);
                Bs[k][n4 + 2] = f2tf32(v.z);
                Bs[k][n4 + 3] = f2tf32(v.w);
            }
        } else {
#pragma unroll
            for (int si = 0; si < 2; si++) {
                int s  = tid + si * 256;
                int n  = s >> 2;              // 0..127
                int kk = (s & 3) * 4;
                int gn = bcol + n;
                float4 v = make_float4(0.f, 0.f, 0.f, 0.f);
                if (gn < Nd && (k0 + kk) < Kd)
                    v = *reinterpret_cast<const float4*>(B + (long long)gn * ldb + k0 + kk);
                Bs[kk + 0][n] = f2tf32(v.x);
                Bs[kk + 1][n] = f2tf32(v.y);
                Bs[kk + 2][n] = f2tf32(v.z);
                Bs[kk + 3][n] = f2tf32(v.w);
            }
        }
        __syncthreads();

#pragma unroll
        for (int ks = 0; ks < BKD; ks += 8) {
            uint32_t af[4][4], bf[4][2];
#pragma unroll
            for (int mt = 0; mt < 4; mt++) {
                int mb = wm * 64 + mt * 16;
                af[mt][0] = As[ks + q    ][mb + g    ];
                af[mt][1] = As[ks + q    ][mb + g + 8];
                af[mt][2] = As[ks + q + 4][mb + g    ];
                af[mt][3] = As[ks + q + 4][mb + g + 8];
            }
#pragma unroll
            for (int nt = 0; nt < 4; nt++) {
                int nb = wn * 32 + nt * 8;
                bf[nt][0] = Bs[ks + q    ][nb + g];
                bf[nt][1] = Bs[ks + q + 4][nb + g];
            }
#pragma unroll
            for (int mt = 0; mt < 4; mt++)
#pragma unroll
                for (int nt = 0; nt < 4; nt++)
                    mma_tf32(acc[mt][nt],
                             af[mt][0], af[mt][1], af[mt][2], af[mt][3],
                             bf[nt][0], bf[nt][1]);
        }
        __syncthreads();
    }

    // ---- epilogue
#pragma unroll
    for (int mt = 0; mt < 4; mt++) {
#pragma unroll
        for (int nt = 0; nt < 4; nt++) {
#pragma unroll
            for (int half = 0; half < 2; half++) {
                int r = brow + wm * 64 + mt * 16 + g + half * 8;
                if (r >= Md) continue;
#pragma unroll
                for (int e = 0; e < 2; e++) {
                    int c = bcol + wn * 32 + nt * 8 + 2 * q + e;
                    if (c >= Nd) continue;
                    float v = acc[mt][nt][half * 2 + e] * alpha;
                    if (EPI >= EPI_BIAS)      v += bias[c];
                    if (EPI == EPI_BIAS_GELU) v = gelu_tanh(v);
                    if (EPI == EPI_BIAS_RES)  v += Res[(long long)r * ldr + c];
                    C[(long long)r * ldc + c] = v;
                }
            }
        }
    }
}

// ---------------------------------------------------------------------------
// Host launcher
// ---------------------------------------------------------------------------
#define SYM(p, s) do { void* _t; cudaGetSymbolAddress(&_t, s); p = (float*)_t; } while (0)

static inline dim3 ggrid(int Md, int Nd, int z) {
    return dim3((Nd + 127) / 128, (Md + 127) / 128, z);
}

extern "C" void kernel_launch(void* const* d_in, const int* in_sizes, int n_in,
                              void* d_out, int out_size)
{
    (void)in_sizes; (void)n_in; (void)out_size;
    const float* pixel    = (const float*)d_in[0];
    const float* patch_w  = (const float*)d_in[2];
    const float* patch_b  = (const float*)d_in[3];
    const float* pos_tab  = (const float*)d_in[4];
    const float* ln1_s    = (const float*)d_in[5];
    const float* ln1_b    = (const float*)d_in[6];
    const float* qkv_w    = (const float*)d_in[7];
    const float* qkv_b    = (const float*)d_in[8];
    const float* proj_w   = (const float*)d_in[9];
    const float* proj_b   = (const float*)d_in[10];
    const float* ln2_s    = (const float*)d_in[11];
    const float* ln2_b    = (const float*)d_in[12];
    const float* fc1_w    = (const float*)d_in[13];
    const float* fc1_b    = (const float*)d_in[14];
    const float* fc2_w    = (const float*)d_in[15];
    const float* fc2_b    = (const float*)d_in[16];
    const float* m_ln_s   = (const float*)d_in[17];
    const float* m_ln_b   = (const float*)d_in[18];
    const float* m_fc1_w  = (const float*)d_in[19];
    const float* m_fc1_b  = (const float*)d_in[20];
    const float* m_fc2_w  = (const float*)d_in[21];
    const float* m_fc2_b  = (const float*)d_in[22];
    float* out = (float*)d_out;

    float *x, *h, *qkv, *attn, *mlp, *logits;
    SYM(x, g_x); SYM(h, g_h); SYM(qkv, g_qkv); SYM(attn, g_attn);
    SYM(mlp, g_mlp); SYM(logits, g_logits);

    const float scale = 0.11785113019775793f;  // 72^-0.5

    cossin_kernel<<<(NTOK * 36 + 255) / 256, 256>>>();

    // Patch embed
    gemm_tc<false, EPI_BIAS><<<ggrid(NTOK, DMODEL, 1), 256>>>(
        pixel, 1536, 0, patch_w, DMODEL, 0, x, DMODEL, 0,
        patch_b, nullptr, 0, NTOK, DMODEL, 1536, 1.0f);

    posadd_kernel<<<NTOK, 288>>>(pos_tab);

    for (int l = 0; l < 2; l++) {
        const float* l1s = ln1_s + l * DMODEL;
        const float* l1b = ln1_b + l * DMODEL;
        const float* qw  = qkv_w + (size_t)l * DMODEL * QKVW;
        const float* qb  = qkv_b + (size_t)l * QKVW;
        const float* pw  = proj_w + (size_t)l * DMODEL * DMODEL;
        const float* pb  = proj_b + (size_t)l * DMODEL;
        const float* l2s = ln2_s + l * DMODEL;
        const float* l2b = ln2_b + l * DMODEL;
        const float* f1w = fc1_w + (size_t)l * DMODEL * IDIM;
        const float* f1b = fc1_b + (size_t)l * IDIM;
        const float* f2w = fc2_w + (size_t)l * IDIM * DMODEL;
        const float* f2b = fc2_b + (size_t)l * DMODEL;

        ln_kernel<<<NTOK, 288>>>(x, h, l1s, l1b);

        gemm_tc<false, EPI_BIAS><<<ggrid(NTOK, QKVW, 1), 256>>>(
            h, DMODEL, 0, qw, QKVW, 0, qkv, QKVW, 0,
            qb, nullptr, 0, NTOK, QKVW, DMODEL, 1.0f);

        rope_kernel<<<NTOK, 576>>>();

        for (int s = 0; s < 4; s++) {
            int st = h_seg_start[s], S = h_seg_len[s];
            const float* qp = qkv + (size_t)st * QKVW;
            const float* kp = qp + DMODEL;
            const float* vp = qp + 2 * DMODEL;
            gemm_tc<true, EPI_NONE><<<ggrid(S, S, HEADS), 256>>>(
                qp, QKVW, HDIM, kp, QKVW, HDIM,
                logits, S, (long long)S * S,
                nullptr, nullptr, 0, S, S, HDIM, scale);
            softmax_kernel<<<HEADS * S, 256>>>(logits, S);
            gemm_tc<false, EPI_NONE><<<ggrid(S, HDIM, HEADS), 256>>>(
                logits, S, (long long)S * S, vp, QKVW, HDIM,
                attn + (size_t)st * DMODEL, DMODEL, HDIM,
                nullptr, nullptr, 0, S, HDIM, S, 1.0f);
        }

        gemm_tc<false, EPI_BIAS_RES><<<ggrid(NTOK, DMODEL, 1), 256>>>(
            attn, DMODEL, 0, pw, DMODEL, 0, x, DMODEL, 0,
            pb, x, DMODEL, NTOK, DMODEL, DMODEL, 1.0f);

        ln_kernel<<<NTOK, 288>>>(x, h, l2s, l2b);

        gemm_tc<false, EPI_BIAS_GELU><<<ggrid(NTOK, IDIM, 1), 256>>>(
            h, DMODEL, 0, f1w, IDIM, 0, mlp, IDIM, 0,
            f1b, nullptr, 0, NTOK, IDIM, DMODEL, 1.0f);

        gemm_tc<false, EPI_BIAS_RES><<<ggrid(NTOK, DMODEL, 1), 256>>>(
            mlp, IDIM, 0, f2w, DMODEL, 0, x, DMODEL, 0,
            f2b, x, DMODEL, NTOK, DMODEL, IDIM, 1.0f);
    }

    // merger
    ln_kernel<<<NTOK, 288>>>(x, h, m_ln_s, m_ln_b);

    gemm_tc<false, EPI_BIAS_GELU><<<ggrid(MROWS, MD, 1), 256>>>(
        h, MD, 0, m_fc1_w, MD, 0, mlp, MD, 0,
        m_fc1_b, nullptr, 0, MROWS, MD, MD, 1.0f);

    gemm_tc<false, EPI_BIAS><<<ggrid(MROWS, DOUT, 1), 256>>>(
        mlp, MD, 0, m_fc2_w, DOUT, 0, out, DOUT, 0,
        m_fc2_b, nullptr, 0, MROWS, DOUT, MD, 1.0f);
}

// round 3
// speedup vs baseline: 2.4870x; 1.0982x over previous
#include <cuda_runtime.h>
#include <math.h>
#include <stdint.h>

// ---------------------------------------------------------------------------
// Problem constants (GRID fixed: [[1,48,48],[1,32,64],[2,24,40]])
// ---------------------------------------------------------------------------
#define NTOK    6272
#define DMODEL  1152
#define HEADS   16
#define HDIM    72
#define IDIM    4304
#define DOUT    2048
#define MROWS   1568
#define MD      4608
#define QKVW    3456

// ---------------------------------------------------------------------------
// Scratch
// ---------------------------------------------------------------------------
__device__ float g_x    [NTOK * DMODEL];
__device__ float g_h    [NTOK * DMODEL];
__device__ float g_qkv  [NTOK * QKVW];
__device__ float g_attn [NTOK * DMODEL];
__device__ float g_mlp  [NTOK * IDIM];
__device__ float g_cos  [NTOK * 36];
__device__ float g_sin  [NTOK * 36];

// ---------------------------------------------------------------------------
__device__ __forceinline__ void token_pos(int n, int& row, int& col, int& ih, int& iw)
{
    int local, h, w;
    if (n < 2304)      { local = n;          h = 48; w = 48; }
    else if (n < 4352) { local = n - 2304;   h = 32; w = 64; }
    else               { local = n - 4352;   h = 24; w = 40; }
    int rem = local % (h * w);
    int wb_cnt = w >> 1;
    int blk = rem >> 2, within = rem & 3;
    int hb = blk / wb_cnt, wb = blk % wb_cnt;
    row = hb * 2 + (within >> 1);
    col = wb * 2 + (within & 1);
    ih = h; iw = w;
}

__global__ void cossin_kernel()
{
    int idx = blockIdx.x * blockDim.x + threadIdx.x;
    if (idx >= NTOK * 36) return;
    int n = idx / 36, d = idx % 36;
    int row, col, ih, iw;
    token_pos(n, row, col, ih, iw);
    int j = (d < 18) ? d : d - 18;
    double p = (d < 18) ? (double)row : (double)col;
    double inv = 1.0 / pow(10000.0, (2.0 * (double)j) / 36.0);
    double ang = p * inv;
    g_cos[idx] = (float)cos(ang);
    g_sin[idx] = (float)sin(ang);
}

__global__ void posadd_kernel(const float* __restrict__ pos_table)
{
    int n = blockIdx.x;
    int row, col, ih, iw;
    token_pos(n, row, col, ih, iw);
    double hi = 47.0 * (double)row / (double)(ih - 1);
    double wi = 47.0 * (double)col / (double)(iw - 1);
    int hf = (int)floor(hi), wf = (int)floor(wi);
    float dh = (float)(hi - (double)hf), dw = (float)(wi - (double)wf);
    int hc = min(hf + 1, 47), wc = min(wf + 1, 47);
    float w00 = (1.f - dh) * (1.f - dw);
    float w01 = (1.f - dh) * dw;
    float w10 = dh * (1.f - dw);
    float w11 = dh * dw;
    const float* p00 = pos_table + (size_t)(hf * 48 + wf) * DMODEL;
    const float* p01 = pos_table + (size_t)(hf * 48 + wc) * DMODEL;
    const float* p10 = pos_table + (size_t)(hc * 48 + wf) * DMODEL;
    const float* p11 = pos_table + (size_t)(hc * 48 + wc) * DMODEL;
    float* xr = g_x + (size_t)n * DMODEL;
    for (int d = threadIdx.x; d < DMODEL; d += blockDim.x)
        xr[d] += p00[d] * w00 + p01[d] * w01 + p10[d] * w10 + p11[d] * w11;
}

__device__ __forceinline__ float warp_sum(float v)
{
#pragma unroll
    for (int o = 16; o > 0; o >>= 1) v += __shfl_xor_sync(0xffffffffu, v, o);
    return v;
}

__global__ void ln_kernel(const float* __restrict__ in, float* __restrict__ out,
                          const float* __restrict__ s, const float* __restrict__ b)
{
    __shared__ float sh[9];
    __shared__ float stat[2];
    int n = blockIdx.x;
    const float* xr = in + (size_t)n * DMODEL;
    int t = threadIdx.x, wid = t >> 5, lane = t & 31;

    float vals[4];
    float lsum = 0.f;
#pragma unroll
    for (int i = 0; i < 4; i++) { vals[i] = xr[t + i * 288]; lsum += vals[i]; }
    float ws = warp_sum(lsum);
    if (lane == 0) sh[wid] = ws;
    __syncthreads();
    if (t == 0) {
        float tot = 0.f;
#pragma unroll
        for (int i = 0; i < 9; i++) tot += sh[i];
        stat[0] = tot * (1.0f / DMODEL);
    }
    __syncthreads();
    float mu = stat[0];
    float lvar = 0.f;
#pragma unroll
    for (int i = 0; i < 4; i++) { float d = vals[i] - mu; lvar += d * d; }
    ws = warp_sum(lvar);
    __syncthreads();
    if (lane == 0) sh[wid] = ws;
    __syncthreads();
    if (t == 0) {
        float tot = 0.f;
#pragma unroll
        for (int i = 0; i < 9; i++) tot += sh[i];
        stat[1] = rsqrtf(tot * (1.0f / DMODEL) + 1e-6f);
    }
    __syncthreads();
    float r = stat[1];
    float* orow = out + (size_t)n * DMODEL;
#pragma unroll
    for (int i = 0; i < 4; i++) {
        int d = t + i * 288;
        orow[d] = (vals[i] - mu) * r * s[d] + b[d];
    }
}

__global__ void rope_kernel()
{
    int n = blockIdx.x;
    int t = threadIdx.x;
    int h = t / 36, d = t % 36;
    float c = g_cos[n * 36 + d];
    float s = g_sin[n * 36 + d];
    float* q = g_qkv + (size_t)n * QKVW + h * HDIM;
    float* k = q + DMODEL;
    float q0 = q[d], q1 = q[d + 36];
    q[d]      = q0 * c - q1 * s;
    q[d + 36] = q1 * c + q0 * s;
    float k0 = k[d], k1 = k[d + 36];
    k[d]      = k0 * c - k1 * s;
    k[d + 36] = k1 * c + k0 * s;
}

// ---------------------------------------------------------------------------
// tf32 helpers
// ---------------------------------------------------------------------------
__device__ __forceinline__ uint32_t f2tf32(float x)
{
    uint32_t r;
    asm("cvt.rna.tf32.f32 %0, %1;" : "=r"(r) : "f"(x));
    return r;
}

__device__ __forceinline__ void mma_tf32(float c[4],
                                         uint32_t a0, uint32_t a1, uint32_t a2, uint32_t a3,
                                         uint32_t b0, uint32_t b1)
{
    asm volatile(
        "mma.sync.aligned.m16n8k8.row.col.f32.tf32.tf32.f32 "
        "{%0,%1,%2,%3}, {%4,%5,%6,%7}, {%8,%9}, {%0,%1,%2,%3};\n"
        : "+f"(c[0]), "+f"(c[1]), "+f"(c[2]), "+f"(c[3])
        : "r"(a0), "r"(a1), "r"(a2), "r"(a3), "r"(b0), "r"(b1));
}

__device__ __forceinline__ float gelu_tanh(float x)
{
    float x3 = x * x * x;
    return 0.5f * x * (1.f + tanhf(0.7978845608028654f * (x + 0.044715f * x3)));
}

// ---------------------------------------------------------------------------
// TF32 tensor-core batched GEMM with register-prefetch pipelining.
//   Block tile 128x128, BK=16, 256 threads (8 warps, 2x4, 64x32 warp tiles).
// ---------------------------------------------------------------------------
#define EPI_NONE      0
#define EPI_BIAS      1
#define EPI_BIAS_GELU 2
#define EPI_BIAS_RES  3

#define BKD 16

template<bool TRANSB, int EPI>
__global__ void __launch_bounds__(256)
gemm_tc(const float* __restrict__ A, int lda, long long sA,
        const float* __restrict__ B, int ldb, long long sB,
        float* __restrict__ C, int ldc, long long sC,
        const float* __restrict__ bias,
        const float* __restrict__ Res, int ldr,
        int Md, int Nd, int Kd, float alpha)
{
    A += (long long)blockIdx.z * sA;
    B += (long long)blockIdx.z * sB;
    C += (long long)blockIdx.z * sC;

    __shared__ uint32_t As[BKD][128 + 4];
    __shared__ uint32_t Bs[BKD][128 + 4];

    const int tid  = threadIdx.x;
    const int brow = blockIdx.y * 128;
    const int bcol = blockIdx.x * 128;
    const int w    = tid >> 5;
    const int lane = tid & 31;
    const int g    = lane >> 2;
    const int q    = lane & 3;
    const int wm   = w & 1;
    const int wn   = w >> 1;

    float acc[4][4][4];
#pragma unroll
    for (int i = 0; i < 4; i++)
#pragma unroll
        for (int j = 0; j < 4; j++)
#pragma unroll
            for (int r = 0; r < 4; r++) acc[i][j][r] = 0.f;

    // per-thread load coordinates
    int am[2], ak[2];
    int bi0[2], bi1[2];
#pragma unroll
    for (int si = 0; si < 2; si++) {
        int s = tid + si * 256;
        am[si] = s >> 2;                 // A m (0..127)
        ak[si] = (s & 3) * 4;            // A k4
        if (!TRANSB) { bi0[si] = s >> 5;  bi1[si] = (s & 31) * 4; }  // k, n4
        else         { bi0[si] = s >> 2;  bi1[si] = (s & 3) * 4;  }  // n, k4
    }

    float4 av[2], bv[2];
    // prologue load (k0 = 0)
#pragma unroll
    for (int si = 0; si < 2; si++) {
        int gr = brow + am[si];
        av[si] = make_float4(0.f, 0.f, 0.f, 0.f);
        if (gr < Md && ak[si] < Kd)
            av[si] = *reinterpret_cast<const float4*>(A + (long long)gr * lda + ak[si]);
        bv[si] = make_float4(0.f, 0.f, 0.f, 0.f);
        if (!TRANSB) {
            int gn = bcol + bi1[si];
            if (gn < Nd && bi0[si] < Kd)
                bv[si] = *reinterpret_cast<const float4*>(B + (long long)bi0[si] * ldb + gn);
        } else {
            int gn = bcol + bi0[si];
            if (gn < Nd && bi1[si] < Kd)
                bv[si] = *reinterpret_cast<const float4*>(B + (long long)gn * ldb + bi1[si]);
        }
    }

    for (int k0 = 0; k0 < Kd; k0 += BKD) {
        // store current tile to smem (with tf32 cvt)
#pragma unroll
        for (int si = 0; si < 2; si++) {
            As[ak[si] + 0][am[si]] = f2tf32(av[si].x);
            As[ak[si] + 1][am[si]] = f2tf32(av[si].y);
            As[ak[si] + 2][am[si]] = f2tf32(av[si].z);
            As[ak[si] + 3][am[si]] = f2tf32(av[si].w);
            if (!TRANSB) {
                Bs[bi0[si]][bi1[si] + 0] = f2tf32(bv[si].x);
                Bs[bi0[si]][bi1[si] + 1] = f2tf32(bv[si].y);
                Bs[bi0[si]][bi1[si] + 2] = f2tf32(bv[si].z);
                Bs[bi0[si]][bi1[si] + 3] = f2tf32(bv[si].w);
            } else {
                Bs[bi1[si] + 0][bi0[si]] = f2tf32(bv[si].x);
                Bs[bi1[si] + 1][bi0[si]] = f2tf32(bv[si].y);
                Bs[bi1[si] + 2][bi0[si]] = f2tf32(bv[si].z);
                Bs[bi1[si] + 3][bi0[si]] = f2tf32(bv[si].w);
            }
        }
        __syncthreads();

        // prefetch next tile into registers (overlaps with mma below)
        int kn = k0 + BKD;
        if (kn < Kd) {
#pragma unroll
            for (int si = 0; si < 2; si++) {
                int gr = brow + am[si];
                av[si] = make_float4(0.f, 0.f, 0.f, 0.f);
                if (gr < Md && (kn + ak[si]) < Kd)
                    av[si] = *reinterpret_cast<const float4*>(A + (long long)gr * lda + kn + ak[si]);
                bv[si] = make_float4(0.f, 0.f, 0.f, 0.f);
                if (!TRANSB) {
                    int gn = bcol + bi1[si];
                    if (gn < Nd && (kn + bi0[si]) < Kd)
                        bv[si] = *reinterpret_cast<const float4*>(B + (long long)(kn + bi0[si]) * ldb + gn);
                } else {
                    int gn = bcol + bi0[si];
                    if (gn < Nd && (kn + bi1[si]) < Kd)
                        bv[si] = *reinterpret_cast<const float4*>(B + (long long)gn * ldb + kn + bi1[si]);
                }
            }
        }

#pragma unroll
        for (int ks = 0; ks < BKD; ks += 8) {
            uint32_t af[4][4], bf[4][2];
#pragma unroll
            for (int mt = 0; mt < 4; mt++) {
                int mb = wm * 64 + mt * 16;
                af[mt][0] = As[ks + q    ][mb + g    ];
                af[mt][1] = As[ks + q    ][mb + g + 8];
                af[mt][2] = As[ks + q + 4][mb + g    ];
                af[mt][3] = As[ks + q + 4][mb + g + 8];
            }
#pragma unroll
            for (int nt = 0; nt < 4; nt++) {
                int nb = wn * 32 + nt * 8;
                bf[nt][0] = Bs[ks + q    ][nb + g];
                bf[nt][1] = Bs[ks + q + 4][nb + g];
            }
#pragma unroll
            for (int mt = 0; mt < 4; mt++)
#pragma unroll
                for (int nt = 0; nt < 4; nt++)
                    mma_tf32(acc[mt][nt],
                             af[mt][0], af[mt][1], af[mt][2], af[mt][3],
                             bf[nt][0], bf[nt][1]);
        }
        __syncthreads();
    }

    // epilogue
#pragma unroll
    for (int mt = 0; mt < 4; mt++) {
#pragma unroll
        for (int nt = 0; nt < 4; nt++) {
#pragma unroll
            for (int half = 0; half < 2; half++) {
                int r = brow + wm * 64 + mt * 16 + g + half * 8;
                if (r >= Md) continue;
#pragma unroll
                for (int e = 0; e < 2; e++) {
                    int c = bcol + wn * 32 + nt * 8 + 2 * q + e;
                    if (c >= Nd) continue;
                    float v = acc[mt][nt][half * 2 + e] * alpha;
                    if (EPI >= EPI_BIAS)      v += bias[c];
                    if (EPI == EPI_BIAS_GELU) v = gelu_tanh(v);
                    if (EPI == EPI_BIAS_RES)  v += Res[(long long)r * ldr + c];
                    C[(long long)r * ldc + c] = v;
                }
            }
        }
    }
}

// ---------------------------------------------------------------------------
// Fused flash attention (tf32 tensor cores, online softmax).
//   One CTA = (q-tile of 128 rows) x (one head).  KV tiles of 64.
//   Smem (dynamic, u32 words):
//     Qs [72][132], Ks [72][68], Vs [64][84], Ps [64][132],
//     m[128], l[128], alpha[128], red[4][128]
// ---------------------------------------------------------------------------
#define QS_OFF   0
#define KS_OFF   (QS_OFF + 72 * 132)
#define VS_OFF   (KS_OFF + 72 * 68)
#define PS_OFF   (VS_OFF + 64 * 84)
#define MS_OFF   (PS_OFF + 64 * 132)
#define LS_OFF   (MS_OFF + 128)
#define AL_OFF   (LS_OFF + 128)
#define RED_OFF  (AL_OFF + 128)
#define FA_WORDS (RED_OFF + 512)
#define FA_BYTES (FA_WORDS * 4)

__global__ void __launch_bounds__(256, 1)
flash_attn(const float* __restrict__ qkv, float* __restrict__ attn)
{
    extern __shared__ uint32_t smem[];
    uint32_t* Qs = smem + QS_OFF;
    uint32_t* Ks = smem + KS_OFF;
    uint32_t* Vs = smem + VS_OFF;
    uint32_t* Ps = smem + PS_OFF;
    float* m_s  = (float*)(smem + MS_OFF);
    float* l_s  = (float*)(smem + LS_OFF);
    float* al_s = (float*)(smem + AL_OFF);
    float* red  = (float*)(smem + RED_OFF);

    int t = blockIdx.x;
    int head = blockIdx.y;
    int st, S, q0;
    if (t < 18)      { st = 0;    S = 2304; q0 = t * 128; }
    else if (t < 34) { st = 2304; S = 2048; q0 = (t - 18) * 128; }
    else if (t < 42) { st = 4352; S = 960;  q0 = (t - 34) * 128; }
    else             { st = 5312; S = 960;  q0 = (t - 42) * 128; }

    const int tid = threadIdx.x;
    const int w = tid >> 5, lane = tid & 31;
    const int g = lane >> 2, q = lane & 3;
    const int wm  = w & 1, wn  = w >> 1;   // QK warp grid 2(M) x 4(N)
    const int wm2 = w & 3, wn2 = w >> 2;   // PV warp grid 4(M) x 2(N)

    const float scale = 0.11785113019775793f;

    // ---- load Q tile once: Qs[hd][row]
    for (int s = tid; s < 128 * 18; s += 256) {
        int row = s / 18, h4 = (s % 18) * 4;
        float4 v = make_float4(0.f, 0.f, 0.f, 0.f);
        if (q0 + row < S)
            v = *reinterpret_cast<const float4*>(
                qkv + (size_t)(st + q0 + row) * QKVW + head * HDIM + h4);
        Qs[(h4 + 0) * 132 + row] = f2tf32(v.x);
        Qs[(h4 + 1) * 132 + row] = f2tf32(v.y);
        Qs[(h4 + 2) * 132 + row] = f2tf32(v.z);
        Qs[(h4 + 3) * 132 + row] = f2tf32(v.w);
    }
    if (tid < 128) { m_s[tid] = -1e30f; l_s[tid] = 0.f; }

    float O[2][5][4];
#pragma unroll
    for (int i = 0; i < 2; i++)
#pragma unroll
        for (int j = 0; j < 5; j++)
#pragma unroll
            for (int r = 0; r < 4; r++) O[i][j][r] = 0.f;

    const int nkv = S >> 6;
    for (int j = 0; j < nkv; j++) {
        __syncthreads();   // prior-iter Ps/Vs/Ks reads done; Q & init visible on j==0
        const int kv0 = j * 64;
        // K tile -> Ks[hd][kv] (transposed)
        for (int s = tid; s < 64 * 18; s += 256) {
            int kv = s / 18, h4 = (s % 18) * 4;
            float4 v = *reinterpret_cast<const float4*>(
                qkv + (size_t)(st + kv0 + kv) * QKVW + DMODEL + head * HDIM + h4);
            Ks[(h4 + 0) * 68 + kv] = f2tf32(v.x);
            Ks[(h4 + 1) * 68 + kv] = f2tf32(v.y);
            Ks[(h4 + 2) * 68 + kv] = f2tf32(v.z);
            Ks[(h4 + 3) * 68 + kv] = f2tf32(v.w);
        }
        // V tile -> Vs[kv][hd]
        for (int s = tid; s < 64 * 18; s += 256) {
            int kv = s / 18, h4 = (s % 18) * 4;
            float4 v = *reinterpret_cast<const float4*>(
                qkv + (size_t)(st + kv0 + kv) * QKVW + 2 * DMODEL + head * HDIM + h4);
            Vs[kv * 84 + h4 + 0] = f2tf32(v.x);
            Vs[kv * 84 + h4 + 1] = f2tf32(v.y);
            Vs[kv * 84 + h4 + 2] = f2tf32(v.z);
            Vs[kv * 84 + h4 + 3] = f2tf32(v.w);
        }
        __syncthreads();

        // ---- S = scale * Q @ K^T   (warp tile 64x16)
        float acc_s[4][2][4];
#pragma unroll
        for (int a = 0; a < 4; a++)
#pragma unroll
            for (int b = 0; b < 2; b++)
#pragma unroll
                for (int r = 0; r < 4; r++) acc_s[a][b][r] = 0.f;

#pragma unroll
        for (int ks = 0; ks < 72; ks += 8) {
            uint32_t af[4][4], bf[2][2];
#pragma unroll
            for (int mt = 0; mt < 4; mt++) {
                int mb = wm * 64 + mt * 16;
                af[mt][0] = Qs[(ks + q    ) * 132 + mb + g    ];
                af[mt][1] = Qs[(ks + q    ) * 132 + mb + g + 8];
                af[mt][2] = Qs[(ks + q + 4) * 132 + mb + g    ];
                af[mt][3] = Qs[(ks + q + 4) * 132 + mb + g + 8];
            }
#pragma unroll
            for (int nt = 0; nt < 2; nt++) {
                int nb = wn * 16 + nt * 8;
                bf[nt][0] = Ks[(ks + q    ) * 68 + nb + g];
                bf[nt][1] = Ks[(ks + q + 4) * 68 + nb + g];
            }
#pragma unroll
            for (int mt = 0; mt < 4; mt++)
#pragma unroll
                for (int nt = 0; nt < 2; nt++)
                    mma_tf32(acc_s[mt][nt],
                             af[mt][0], af[mt][1], af[mt][2], af[mt][3],
                             bf[nt][0], bf[nt][1]);
        }
#pragma unroll
        for (int a = 0; a < 4; a++)
#pragma unroll
            for (int b = 0; b < 2; b++)
#pragma unroll
                for (int r = 0; r < 4; r++) acc_s[a][b][r] *= scale;

        // ---- row max (warp partial + cross-warp via smem)
#pragma unroll
        for (int mt = 0; mt < 4; mt++) {
#pragma unroll
            for (int h = 0; h < 2; h++) {
                float rmx = fmaxf(fmaxf(acc_s[mt][0][2 * h], acc_s[mt][0][2 * h + 1]),
                                  fmaxf(acc_s[mt][1][2 * h], acc_s[mt][1][2 * h + 1]));
                rmx = fmaxf(rmx, __shfl_xor_sync(0xffffffffu, rmx, 1));
                rmx = fmaxf(rmx, __shfl_xor_sync(0xffffffffu, rmx, 2));
                if (q == 0)
                    red[wn * 128 + wm * 64 + mt * 16 + g + 8 * h] = rmx;
            }
        }
        __syncthreads();
        if (tid < 128) {
            float tm = fmaxf(fmaxf(red[tid], red[128 + tid]),
                             fmaxf(red[256 + tid], red[384 + tid]));
            float mo = m_s[tid];
            float mn = fmaxf(mo, tm);
            al_s[tid] = __expf(mo - mn);
            m_s[tid]  = mn;
        }
        __syncthreads();

        // ---- P~ = exp(S - m_new) -> Ps (tf32); row sums; rescale O
#pragma unroll
        for (int mt = 0; mt < 4; mt++) {
#pragma unroll
            for (int h = 0; h < 2; h++) {
                int row = wm * 64 + mt * 16 + g + 8 * h;
                float mn = m_s[row];
                float rs = 0.f;
#pragma unroll
                for (int nt = 0; nt < 2; nt++) {
#pragma unroll
                    for (int e = 0; e < 2; e++) {
                        float p = __expf(acc_s[mt][nt][2 * h + e] - mn);
                        rs += p;
                        int col = wn * 16 + nt * 8 + 2 * q + e;
                        Ps[col * 132 + row] = f2tf32(p);
                    }
                }
                rs += __shfl_xor_sync(0xffffffffu, rs, 1);
                rs += __shfl_xor_sync(0xffffffffu, rs, 2);
                if (q == 0) red[wn * 128 + row] = rs;
            }
        }
        // rescale O by alpha (PV row ownership)
#pragma unroll
        for (int mt = 0; mt < 2; mt++) {
#pragma unroll
            for (int h = 0; h < 2; h++) {
                int row = wm2 * 32 + mt * 16 + g + 8 * h;
                float a = al_s[row];
#pragma unroll
                for (int nt = 0; nt < 5; nt++) {
                    O[mt][nt][2 * h + 0] *= a;
                    O[mt][nt][2 * h + 1] *= a;
                }
            }
        }
        __syncthreads();
        if (tid < 128)
            l_s[tid] = l_s[tid] * al_s[tid] +
                       red[tid] + red[128 + tid] + red[256 + tid] + red[384 + tid];

        // ---- O += P~ @ V   (warp tile 32x40)
#pragma unroll
        for (int ks = 0; ks < 64; ks += 8) {
            uint32_t af[2][4], bf[5][2];
#pragma unroll
            for (int mt = 0; mt < 2; mt++) {
                int mb = wm2 * 32 + mt * 16;
                af[mt][0] = Ps[(ks + q    ) * 132 + mb + g    ];
                af[mt][1] = Ps[(ks + q    ) * 132 + mb + g + 8];
                af[mt][2] = Ps[(ks + q + 4) * 132 + mb + g    ];
                af[mt][3] = Ps[(ks + q + 4) * 132 + mb + g + 8];
            }
#pragma unroll
            for (int nt = 0; nt < 5; nt++) {
                int nb = wn2 * 40 + nt * 8;
                bf[nt][0] = Vs[(ks + q    ) * 84 + nb + g];
                bf[nt][1] = Vs[(ks + q + 4) * 84 + nb + g];
            }
#pragma unroll
            for (int mt = 0; mt < 2; mt++)
#pragma unroll
                for (int nt = 0; nt < 5; nt++)
                    mma_tf32(O[mt][nt],
                             af[mt][0], af[mt][1], af[mt][2], af[mt][3],
                             bf[nt][0], bf[nt][1]);
        }
    }
    __syncthreads();

    // ---- epilogue: O / l -> attn[:, head*72 : head*72+72]
#pragma unroll
    for (int mt = 0; mt < 2; mt++) {
#pragma unroll
        for (int h = 0; h < 2; h++) {
            int r = wm2 * 32 + mt * 16 + g + 8 * h;
            if (q0 + r >= S) continue;
            float inv = 1.0f / l_s[r];
#pragma unroll
            for (int nt = 0; nt < 5; nt++) {
#pragma unroll
                for (int e = 0; e < 2; e++) {
                    int c = wn2 * 40 + nt * 8 + 2 * q + e;
                    if (c < HDIM)
                        attn[(size_t)(st + q0 + r) * DMODEL + head * HDIM + c] =
                            O[mt][nt][2 * h + e] * inv;
                }
            }
        }
    }
}

// ---------------------------------------------------------------------------
// Host launcher
// ---------------------------------------------------------------------------
#define SYM(p, s) do { void* _t; cudaGetSymbolAddress(&_t, s); p = (float*)_t; } while (0)

static inline dim3 ggrid(int Md, int Nd, int z) {
    return dim3((Nd + 127) / 128, (Md + 127) / 128, z);
}

extern "C" void kernel_launch(void* const* d_in, const int* in_sizes, int n_in,
                              void* d_out, int out_size)
{
    (void)in_sizes; (void)n_in; (void)out_size;
    const float* pixel    = (const float*)d_in[0];
    const float* patch_w  = (const float*)d_in[2];
    const float* patch_b  = (const float*)d_in[3];
    const float* pos_tab  = (const float*)d_in[4];
    const float* ln1_s    = (const float*)d_in[5];
    const float* ln1_b    = (const float*)d_in[6];
    const float* qkv_w    = (const float*)d_in[7];
    const float* qkv_b    = (const float*)d_in[8];
    const float* proj_w   = (const float*)d_in[9];
    const float* proj_b   = (const float*)d_in[10];
    const float* ln2_s    = (const float*)d_in[11];
    const float* ln2_b    = (const float*)d_in[12];
    const float* fc1_w    = (const float*)d_in[13];
    const float* fc1_b    = (const float*)d_in[14];
    const float* fc2_w    = (const float*)d_in[15];
    const float* fc2_b    = (const float*)d_in[16];
    const float* m_ln_s   = (const float*)d_in[17];
    const float* m_ln_b   = (const float*)d_in[18];
    const float* m_fc1_w  = (const float*)d_in[19];
    const float* m_fc1_b  = (const float*)d_in[20];
    const float* m_fc2_w  = (const float*)d_in[21];
    const float* m_fc2_b  = (const float*)d_in[22];
    float* out = (float*)d_out;

    float *x, *h, *qkv, *attn, *mlp;
    SYM(x, g_x); SYM(h, g_h); SYM(qkv, g_qkv); SYM(attn, g_attn);
    SYM(mlp, g_mlp);

    static bool attr_set = false;
    if (!attr_set) {
        cudaFuncSetAttribute(flash_attn,
                             cudaFuncAttributeMaxDynamicSharedMemorySize, FA_BYTES);
        attr_set = true;
    }

    cossin_kernel<<<(NTOK * 36 + 255) / 256, 256>>>();

    // Patch embed
    gemm_tc<false, EPI_BIAS><<<ggrid(NTOK, DMODEL, 1), 256>>>(
        pixel, 1536, 0, patch_w, DMODEL, 0, x, DMODEL, 0,
        patch_b, nullptr, 0, NTOK, DMODEL, 1536, 1.0f);

    posadd_kernel<<<NTOK, 288>>>(pos_tab);

    for (int l = 0; l < 2; l++) {
        const float* l1s = ln1_s + l * DMODEL;
        const float* l1b = ln1_b + l * DMODEL;
        const float* qw  = qkv_w + (size_t)l * DMODEL * QKVW;
        const float* qb  = qkv_b + (size_t)l * QKVW;
        const float* pw  = proj_w + (size_t)l * DMODEL * DMODEL;
        const float* pb  = proj_b + (size_t)l * DMODEL;
        const float* l2s = ln2_s + l * DMODEL;
        const float* l2b = ln2_b + l * DMODEL;
        const float* f1w = fc1_w + (size_t)l * DMODEL * IDIM;
        const float* f1b = fc1_b + (size_t)l * IDIM;
        const float* f2w = fc2_w + (size_t)l * IDIM * DMODEL;
        const float* f2b = fc2_b + (size_t)l * DMODEL;

        ln_kernel<<<NTOK, 288>>>(x, h, l1s, l1b);

        gemm_tc<false, EPI_BIAS><<<ggrid(NTOK, QKVW, 1), 256>>>(
            h, DMODEL, 0, qw, QKVW, 0, qkv, QKVW, 0,
            qb, nullptr, 0, NTOK, QKVW, DMODEL, 1.0f);

        rope_kernel<<<NTOK, 576>>>();

        flash_attn<<<dim3(50, HEADS), 256, FA_BYTES>>>(qkv, attn);

        gemm_tc<false, EPI_BIAS_RES><<<ggrid(NTOK, DMODEL, 1), 256>>>(
            attn, DMODEL, 0, pw, DMODEL, 0, x, DMODEL, 0,
            pb, x, DMODEL, NTOK, DMODEL, DMODEL, 1.0f);

        ln_kernel<<<NTOK, 288>>>(x, h, l2s, l2b);

        gemm_tc<false, EPI_BIAS_GELU><<<ggrid(NTOK, IDIM, 1), 256>>>(
            h, DMODEL, 0, f1w, IDIM, 0, mlp, IDIM, 0,
            f1b, nullptr, 0, NTOK, IDIM, DMODEL, 1.0f);

        gemm_tc<false, EPI_BIAS_RES><<<ggrid(NTOK, DMODEL, 1), 256>>>(
            mlp, IDIM, 0, f2w, DMODEL, 0, x, DMODEL, 0,
            f2b, x, DMODEL, NTOK, DMODEL, IDIM, 1.0f);
    }

    // merger
    ln_kernel<<<NTOK, 288>>>(x, h, m_ln_s, m_ln_b);

    gemm_tc<false, EPI_BIAS_GELU><<<ggrid(MROWS, MD, 1), 256>>>(
        h, MD, 0, m_fc1_w, MD, 0, mlp, MD, 0,
        m_fc1_b, nullptr, 0, MROWS, MD, MD, 1.0f);

    gemm_tc<false, EPI_BIAS><<<ggrid(MROWS, DOUT, 1), 256>>>(
        mlp, MD, 0, m_fc2_w, DOUT, 0, out, DOUT, 0,
        m_fc2_b, nullptr, 0, MROWS, DOUT, MD, 1.0f);
}

// round 4
// speedup vs baseline: 2.5287x; 1.0168x over previous
#include <cuda_runtime.h>
#include <math.h>
#include <stdint.h>

// ---------------------------------------------------------------------------
// Problem constants (GRID fixed: [[1,48,48],[1,32,64],[2,24,40]])
// ---------------------------------------------------------------------------
#define NTOK    6272
#define DMODEL  1152
#define HEADS   16
#define HDIM    72
#define IDIM    4304
#define DOUT    2048
#define MROWS   1568
#define MD      4608
#define QKVW    3456

// ---------------------------------------------------------------------------
// Scratch
// ---------------------------------------------------------------------------
__device__ float g_x    [NTOK * DMODEL];
__device__ float g_h    [NTOK * DMODEL];
__device__ float g_qkv  [NTOK * QKVW];
__device__ float g_attn [NTOK * DMODEL];
__device__ float g_mlp  [NTOK * IDIM];
__device__ float g_cos  [NTOK * 36];
__device__ float g_sin  [NTOK * 36];

// ---------------------------------------------------------------------------
__device__ __forceinline__ void token_pos(int n, int& row, int& col, int& ih, int& iw)
{
    int local, h, w;
    if (n < 2304)      { local = n;          h = 48; w = 48; }
    else if (n < 4352) { local = n - 2304;   h = 32; w = 64; }
    else               { local = n - 4352;   h = 24; w = 40; }
    int rem = local % (h * w);
    int wb_cnt = w >> 1;
    int blk = rem >> 2, within = rem & 3;
    int hb = blk / wb_cnt, wb = blk % wb_cnt;
    row = hb * 2 + (within >> 1);
    col = wb * 2 + (within & 1);
    ih = h; iw = w;
}

__global__ void cossin_kernel()
{
    int idx = blockIdx.x * blockDim.x + threadIdx.x;
    if (idx >= NTOK * 36) return;
    int n = idx / 36, d = idx % 36;
    int row, col, ih, iw;
    token_pos(n, row, col, ih, iw);
    int j = (d < 18) ? d : d - 18;
    double p = (d < 18) ? (double)row : (double)col;
    double inv = 1.0 / pow(10000.0, (2.0 * (double)j) / 36.0);
    double ang = p * inv;
    g_cos[idx] = (float)cos(ang);
    g_sin[idx] = (float)sin(ang);
}

__global__ void posadd_kernel(const float* __restrict__ pos_table)
{
    int n = blockIdx.x;
    int row, col, ih, iw;
    token_pos(n, row, col, ih, iw);
    double hi = 47.0 * (double)row / (double)(ih - 1);
    double wi = 47.0 * (double)col / (double)(iw - 1);
    int hf = (int)floor(hi), wf = (int)floor(wi);
    float dh = (float)(hi - (double)hf), dw = (float)(wi - (double)wf);
    int hc = min(hf + 1, 47), wc = min(wf + 1, 47);
    float w00 = (1.f - dh) * (1.f - dw);
    float w01 = (1.f - dh) * dw;
    float w10 = dh * (1.f - dw);
    float w11 = dh * dw;
    const float* p00 = pos_table + (size_t)(hf * 48 + wf) * DMODEL;
    const float* p01 = pos_table + (size_t)(hf * 48 + wc) * DMODEL;
    const float* p10 = pos_table + (size_t)(hc * 48 + wf) * DMODEL;
    const float* p11 = pos_table + (size_t)(hc * 48 + wc) * DMODEL;
    float* xr = g_x + (size_t)n * DMODEL;
    for (int d = threadIdx.x; d < DMODEL; d += blockDim.x)
        xr[d] += p00[d] * w00 + p01[d] * w01 + p10[d] * w10 + p11[d] * w11;
}

__device__ __forceinline__ float warp_sum(float v)
{
#pragma unroll
    for (int o = 16; o > 0; o >>= 1) v += __shfl_xor_sync(0xffffffffu, v, o);
    return v;
}

__global__ void ln_kernel(const float* __restrict__ in, float* __restrict__ out,
                          const float* __restrict__ s, const float* __restrict__ b)
{
    __shared__ float sh[9];
    __shared__ float stat[2];
    int n = blockIdx.x;
    const float* xr = in + (size_t)n * DMODEL;
    int t = threadIdx.x, wid = t >> 5, lane = t & 31;

    float vals[4];
    float lsum = 0.f;
#pragma unroll
    for (int i = 0; i < 4; i++) { vals[i] = xr[t + i * 288]; lsum += vals[i]; }
    float ws = warp_sum(lsum);
    if (lane == 0) sh[wid] = ws;
    __syncthreads();
    if (t == 0) {
        float tot = 0.f;
#pragma unroll
        for (int i = 0; i < 9; i++) tot += sh[i];
        stat[0] = tot * (1.0f / DMODEL);
    }
    __syncthreads();
    float mu = stat[0];
    float lvar = 0.f;
#pragma unroll
    for (int i = 0; i < 4; i++) { float d = vals[i] - mu; lvar += d * d; }
    ws = warp_sum(lvar);
    __syncthreads();
    if (lane == 0) sh[wid] = ws;
    __syncthreads();
    if (t == 0) {
        float tot = 0.f;
#pragma unroll
        for (int i = 0; i < 9; i++) tot += sh[i];
        stat[1] = rsqrtf(tot * (1.0f / DMODEL) + 1e-6f);
    }
    __syncthreads();
    float r = stat[1];
    float* orow = out + (size_t)n * DMODEL;
#pragma unroll
    for (int i = 0; i < 4; i++) {
        int d = t + i * 288;
        orow[d] = (vals[i] - mu) * r * s[d] + b[d];
    }
}

__global__ void rope_kernel()
{
    int n = blockIdx.x;
    int t = threadIdx.x;
    int h = t / 36, d = t % 36;
    float c = g_cos[n * 36 + d];
    float s = g_sin[n * 36 + d];
    float* q = g_qkv + (size_t)n * QKVW + h * HDIM;
    float* k = q + DMODEL;
    float q0 = q[d], q1 = q[d + 36];
    q[d]      = q0 * c - q1 * s;
    q[d + 36] = q1 * c + q0 * s;
    float k0 = k[d], k1 = k[d + 36];
    k[d]      = k0 * c - k1 * s;
    k[d + 36] = k1 * c + k0 * s;
}

// ---------------------------------------------------------------------------
// tf32 helpers
// ---------------------------------------------------------------------------
__device__ __forceinline__ uint32_t f2tf32(float x)
{
    uint32_t r;
    asm("cvt.rna.tf32.f32 %0, %1;" : "=r"(r) : "f"(x));
    return r;
}

__device__ __forceinline__ void mma_tf32(float c[4],
                                         uint32_t a0, uint32_t a1, uint32_t a2, uint32_t a3,
                                         uint32_t b0, uint32_t b1)
{
    asm volatile(
        "mma.sync.aligned.m16n8k8.row.col.f32.tf32.tf32.f32 "
        "{%0,%1,%2,%3}, {%4,%5,%6,%7}, {%8,%9}, {%0,%1,%2,%3};\n"
        : "+f"(c[0]), "+f"(c[1]), "+f"(c[2]), "+f"(c[3])
        : "r"(a0), "r"(a1), "r"(a2), "r"(a3), "r"(b0), "r"(b1));
}

__device__ __forceinline__ float gelu_tanh(float x)
{
    float x3 = x * x * x;
    return 0.5f * x * (1.f + tanhf(0.7978845608028654f * (x + 0.044715f * x3)));
}

// ---------------------------------------------------------------------------
// TF32 tensor-core GEMM v2 (non-transposed B only).
//   Block 256x128, BK=16, 8 warps (4M x 2N), warp tile 64x64.
//   Double-buffered smem, conflict-free layouts:
//     As [m][k]: row stride 20 words  (frag bank = (20g+q)&31, all distinct)
//     Bs [k][n]: row stride 136 words (frag bank = (8q+g)&31, all distinct)
// ---------------------------------------------------------------------------
#define EPI_BIAS      1
#define EPI_BIAS_GELU 2
#define EPI_BIAS_RES  3

#define G2_BM 256
#define G2_BN 128
#define G2_AST 20
#define G2_BST 136
#define G2_ASTAGE (G2_BM * G2_AST)          // 5120 words
#define G2_BSTAGE (16 * G2_BST)             // 2176 words
#define G2_SMEM_BYTES ((2 * G2_ASTAGE + 2 * G2_BSTAGE) * 4)   // 58368

template<int EPI>
__global__ void __launch_bounds__(256, 1)
gemm_tc2(const float* __restrict__ A, int lda,
         const float* __restrict__ B, int ldb,
         float* __restrict__ C, int ldc,
         const float* __restrict__ bias,
         const float* __restrict__ Res, int ldr,
         int Md, int Nd, int Kd)
{
    extern __shared__ uint32_t sm[];
    uint32_t* AsBase = sm;
    uint32_t* BsBase = sm + 2 * G2_ASTAGE;

    const int tid  = threadIdx.x;
    const int brow = blockIdx.y * G2_BM;
    const int bcol = blockIdx.x * G2_BN;
    const int w    = tid >> 5;
    const int lane = tid & 31;
    const int g    = lane >> 2;
    const int q    = lane & 3;
    const int wm   = w & 3;          // 4 warps in M
    const int wn   = w >> 2;         // 2 warps in N

    float acc[4][8][4];
#pragma unroll
    for (int i = 0; i < 4; i++)
#pragma unroll
        for (int j = 0; j < 8; j++)
#pragma unroll
            for (int r = 0; r < 4; r++) acc[i][j][r] = 0.f;

    // load coordinates
    int am[4], ak[4], bk[2], bn[2];
#pragma unroll
    for (int i = 0; i < 4; i++) {
        int s = tid + i * 256;
        am[i] = s >> 2;              // 0..255
        ak[i] = (s & 3) * 4;         // 0,4,8,12
    }
#pragma unroll
    for (int i = 0; i < 2; i++) {
        int s = tid + i * 256;
        bk[i] = s >> 5;              // 0..15
        bn[i] = (s & 31) * 4;        // 0..124
    }

    float4 av[4], bv[2];
    // prologue (k0 = 0)
#pragma unroll
    for (int i = 0; i < 4; i++) {
        int gr = brow + am[i];
        av[i] = make_float4(0.f, 0.f, 0.f, 0.f);
        if (gr < Md)
            av[i] = *reinterpret_cast<const float4*>(A + (long long)gr * lda + ak[i]);
    }
#pragma unroll
    for (int i = 0; i < 2; i++) {
        int gn = bcol + bn[i];
        bv[i] = make_float4(0.f, 0.f, 0.f, 0.f);
        if (gn < Nd)
            bv[i] = *reinterpret_cast<const float4*>(B + (long long)bk[i] * ldb + gn);
    }
    // store stage 0
#pragma unroll
    for (int i = 0; i < 4; i++) {
        uint4 t = make_uint4(f2tf32(av[i].x), f2tf32(av[i].y), f2tf32(av[i].z), f2tf32(av[i].w));
        *reinterpret_cast<uint4*>(&AsBase[am[i] * G2_AST + ak[i]]) = t;
    }
#pragma unroll
    for (int i = 0; i < 2; i++) {
        uint4 t = make_uint4(f2tf32(bv[i].x), f2tf32(bv[i].y), f2tf32(bv[i].z), f2tf32(bv[i].w));
        *reinterpret_cast<uint4*>(&BsBase[bk[i] * G2_BST + bn[i]]) = t;
    }
    __syncthreads();

    const int ntiles = Kd >> 4;
    for (int kt = 0; kt < ntiles; kt++) {
        const int buf = kt & 1;
        const bool more = (kt + 1 < ntiles);
        if (more) {
            int k0 = (kt + 1) << 4;
#pragma unroll
            for (int i = 0; i < 4; i++) {
                int gr = brow + am[i];
                av[i] = make_float4(0.f, 0.f, 0.f, 0.f);
                if (gr < Md)
                    av[i] = *reinterpret_cast<const float4*>(A + (long long)gr * lda + k0 + ak[i]);
            }
#pragma unroll
            for (int i = 0; i < 2; i++) {
                int gn = bcol + bn[i];
                bv[i] = make_float4(0.f, 0.f, 0.f, 0.f);
                if (gn < Nd)
                    bv[i] = *reinterpret_cast<const float4*>(B + (long long)(k0 + bk[i]) * ldb + gn);
            }
        }

        const uint32_t* Ab = AsBase + buf * G2_ASTAGE;
        const uint32_t* Bb = BsBase + buf * G2_BSTAGE;
#pragma unroll
        for (int ks = 0; ks < 16; ks += 8) {
            uint32_t afr[4][4], bfr[8][2];
#pragma unroll
            for (int mt = 0; mt < 4; mt++) {
                int mb = wm * 64 + mt * 16;
                afr[mt][0] = Ab[(mb + g    ) * G2_AST + ks + q    ];
                afr[mt][1] = Ab[(mb + g + 8) * G2_AST + ks + q    ];
                afr[mt][2] = Ab[(mb + g    ) * G2_AST + ks + q + 4];
                afr[mt][3] = Ab[(mb + g + 8) * G2_AST + ks + q + 4];
            }
#pragma unroll
            for (int nt = 0; nt < 8; nt++) {
                int nb = wn * 64 + nt * 8;
                bfr[nt][0] = Bb[(ks + q    ) * G2_BST + nb + g];
                bfr[nt][1] = Bb[(ks + q + 4) * G2_BST + nb + g];
            }
#pragma unroll
            for (int mt = 0; mt < 4; mt++)
#pragma unroll
                for (int nt = 0; nt < 8; nt++)
                    mma_tf32(acc[mt][nt],
                             afr[mt][0], afr[mt][1], afr[mt][2], afr[mt][3],
                             bfr[nt][0], bfr[nt][1]);
        }

        if (more) {
            uint32_t* An = AsBase + (buf ^ 1) * G2_ASTAGE;
            uint32_t* Bn = BsBase + (buf ^ 1) * G2_BSTAGE;
#pragma unroll
            for (int i = 0; i < 4; i++) {
                uint4 t = make_uint4(f2tf32(av[i].x), f2tf32(av[i].y), f2tf32(av[i].z), f2tf32(av[i].w));
                *reinterpret_cast<uint4*>(&An[am[i] * G2_AST + ak[i]]) = t;
            }
#pragma unroll
            for (int i = 0; i < 2; i++) {
                uint4 t = make_uint4(f2tf32(bv[i].x), f2tf32(bv[i].y), f2tf32(bv[i].z), f2tf32(bv[i].w));
                *reinterpret_cast<uint4*>(&Bn[bk[i] * G2_BST + bn[i]]) = t;
            }
        }
        __syncthreads();
    }

    // epilogue (paired float2 stores where possible)
#pragma unroll
    for (int mt = 0; mt < 4; mt++) {
#pragma unroll
        for (int half = 0; half < 2; half++) {
            int r = brow + wm * 64 + mt * 16 + g + 8 * half;
            if (r >= Md) continue;
#pragma unroll
            for (int nt = 0; nt < 8; nt++) {
                int c = bcol + wn * 64 + nt * 8 + 2 * q;
                if (c + 1 >= Nd) {
                    if (c < Nd) {
                        float v = acc[mt][nt][half * 2];
                        if (EPI >= EPI_BIAS)      v += bias[c];
                        if (EPI == EPI_BIAS_GELU) v = gelu_tanh(v);
                        if (EPI == EPI_BIAS_RES)  v += Res[(long long)r * ldr + c];
                        C[(long long)r * ldc + c] = v;
                    }
                    continue;
                }
                float v0 = acc[mt][nt][half * 2];
                float v1 = acc[mt][nt][half * 2 + 1];
                if (EPI >= EPI_BIAS)      { v0 += bias[c]; v1 += bias[c + 1]; }
                if (EPI == EPI_BIAS_GELU) { v0 = gelu_tanh(v0); v1 = gelu_tanh(v1); }
                if (EPI == EPI_BIAS_RES)  {
                    v0 += Res[(long long)r * ldr + c];
                    v1 += Res[(long long)r * ldr + c + 1];
                }
                *reinterpret_cast<float2*>(C + (long long)r * ldc + c) = make_float2(v0, v1);
            }
        }
    }
}

// ---------------------------------------------------------------------------
// Fused flash attention (tf32 tensor cores, online softmax).  Unchanged.
// ---------------------------------------------------------------------------
#define QS_OFF   0
#define KS_OFF   (QS_OFF + 72 * 132)
#define VS_OFF   (KS_OFF + 72 * 68)
#define PS_OFF   (VS_OFF + 64 * 84)
#define MS_OFF   (PS_OFF + 64 * 132)
#define LS_OFF   (MS_OFF + 128)
#define AL_OFF   (LS_OFF + 128)
#define RED_OFF  (AL_OFF + 128)
#define FA_WORDS (RED_OFF + 512)
#define FA_BYTES (FA_WORDS * 4)

__global__ void __launch_bounds__(256, 1)
flash_attn(const float* __restrict__ qkv, float* __restrict__ attn)
{
    extern __shared__ uint32_t smem[];
    uint32_t* Qs = smem + QS_OFF;
    uint32_t* Ks = smem + KS_OFF;
    uint32_t* Vs = smem + VS_OFF;
    uint32_t* Ps = smem + PS_OFF;
    float* m_s  = (float*)(smem + MS_OFF);
    float* l_s  = (float*)(smem + LS_OFF);
    float* al_s = (float*)(smem + AL_OFF);
    float* red  = (float*)(smem + RED_OFF);

    int t = blockIdx.x;
    int head = blockIdx.y;
    int st, S, q0;
    if (t < 18)      { st = 0;    S = 2304; q0 = t * 128; }
    else if (t < 34) { st = 2304; S = 2048; q0 = (t - 18) * 128; }
    else if (t < 42) { st = 4352; S = 960;  q0 = (t - 34) * 128; }
    else             { st = 5312; S = 960;  q0 = (t - 42) * 128; }

    const int tid = threadIdx.x;
    const int w = tid >> 5, lane = tid & 31;
    const int g = lane >> 2, q = lane & 3;
    const int wm  = w & 1, wn  = w >> 1;
    const int wm2 = w & 3, wn2 = w >> 2;

    const float scale = 0.11785113019775793f;

    for (int s = tid; s < 128 * 18; s += 256) {
        int row = s / 18, h4 = (s % 18) * 4;
        float4 v = make_float4(0.f, 0.f, 0.f, 0.f);
        if (q0 + row < S)
            v = *reinterpret_cast<const float4*>(
                qkv + (size_t)(st + q0 + row) * QKVW + head * HDIM + h4);
        Qs[(h4 + 0) * 132 + row] = f2tf32(v.x);
        Qs[(h4 + 1) * 132 + row] = f2tf32(v.y);
        Qs[(h4 + 2) * 132 + row] = f2tf32(v.z);
        Qs[(h4 + 3) * 132 + row] = f2tf32(v.w);
    }
    if (tid < 128) { m_s[tid] = -1e30f; l_s[tid] = 0.f; }

    float O[2][5][4];
#pragma unroll
    for (int i = 0; i < 2; i++)
#pragma unroll
        for (int j = 0; j < 5; j++)
#pragma unroll
            for (int r = 0; r < 4; r++) O[i][j][r] = 0.f;

    const int nkv = S >> 6;
    for (int j = 0; j < nkv; j++) {
        __syncthreads();
        const int kv0 = j * 64;
        for (int s = tid; s < 64 * 18; s += 256) {
            int kv = s / 18, h4 = (s % 18) * 4;
            float4 v = *reinterpret_cast<const float4*>(
                qkv + (size_t)(st + kv0 + kv) * QKVW + DMODEL + head * HDIM + h4);
            Ks[(h4 + 0) * 68 + kv] = f2tf32(v.x);
            Ks[(h4 + 1) * 68 + kv] = f2tf32(v.y);
            Ks[(h4 + 2) * 68 + kv] = f2tf32(v.z);
            Ks[(h4 + 3) * 68 + kv] = f2tf32(v.w);
        }
        for (int s = tid; s < 64 * 18; s += 256) {
            int kv = s / 18, h4 = (s % 18) * 4;
            float4 v = *reinterpret_cast<const float4*>(
                qkv + (size_t)(st + kv0 + kv) * QKVW + 2 * DMODEL + head * HDIM + h4);
            Vs[kv * 84 + h4 + 0] = f2tf32(v.x);
            Vs[kv * 84 + h4 + 1] = f2tf32(v.y);
            Vs[kv * 84 + h4 + 2] = f2tf32(v.z);
            Vs[kv * 84 + h4 + 3] = f2tf32(v.w);
        }
        __syncthreads();

        float acc_s[4][2][4];
#pragma unroll
        for (int a = 0; a < 4; a++)
#pragma unroll
            for (int b = 0; b < 2; b++)
#pragma unroll
                for (int r = 0; r < 4; r++) acc_s[a][b][r] = 0.f;

#pragma unroll
        for (int ks = 0; ks < 72; ks += 8) {
            uint32_t af[4][4], bf[2][2];
#pragma unroll
            for (int mt = 0; mt < 4; mt++) {
                int mb = wm * 64 + mt * 16;
                af[mt][0] = Qs[(ks + q    ) * 132 + mb + g    ];
                af[mt][1] = Qs[(ks + q    ) * 132 + mb + g + 8];
                af[mt][2] = Qs[(ks + q + 4) * 132 + mb + g    ];
                af[mt][3] = Qs[(ks + q + 4) * 132 + mb + g + 8];
            }
#pragma unroll
            for (int nt = 0; nt < 2; nt++) {
                int nb = wn * 16 + nt * 8;
                bf[nt][0] = Ks[(ks + q    ) * 68 + nb + g];
                bf[nt][1] = Ks[(ks + q + 4) * 68 + nb + g];
            }
#pragma unroll
            for (int mt = 0; mt < 4; mt++)
#pragma unroll
                for (int nt = 0; nt < 2; nt++)
                    mma_tf32(acc_s[mt][nt],
                             af[mt][0], af[mt][1], af[mt][2], af[mt][3],
                             bf[nt][0], bf[nt][1]);
        }
#pragma unroll
        for (int a = 0; a < 4; a++)
#pragma unroll
            for (int b = 0; b < 2; b++)
#pragma unroll
                for (int r = 0; r < 4; r++) acc_s[a][b][r] *= scale;

#pragma unroll
        for (int mt = 0; mt < 4; mt++) {
#pragma unroll
            for (int h = 0; h < 2; h++) {
                float rmx = fmaxf(fmaxf(acc_s[mt][0][2 * h], acc_s[mt][0][2 * h + 1]),
                                  fmaxf(acc_s[mt][1][2 * h], acc_s[mt][1][2 * h + 1]));
                rmx = fmaxf(rmx, __shfl_xor_sync(0xffffffffu, rmx, 1));
                rmx = fmaxf(rmx, __shfl_xor_sync(0xffffffffu, rmx, 2));
                if (q == 0)
                    red[wn * 128 + wm * 64 + mt * 16 + g + 8 * h] = rmx;
            }
        }
        __syncthreads();
        if (tid < 128) {
            float tm = fmaxf(fmaxf(red[tid], red[128 + tid]),
                             fmaxf(red[256 + tid], red[384 + tid]));
            float mo = m_s[tid];
            float mn = fmaxf(mo, tm);
            al_s[tid] = __expf(mo - mn);
            m_s[tid]  = mn;
        }
        __syncthreads();

#pragma unroll
        for (int mt = 0; mt < 4; mt++) {
#pragma unroll
            for (int h = 0; h < 2; h++) {
                int row = wm * 64 + mt * 16 + g + 8 * h;
                float mn = m_s[row];
                float rs = 0.f;
#pragma unroll
                for (int nt = 0; nt < 2; nt++) {
#pragma unroll
                    for (int e = 0; e < 2; e++) {
                        float p = __expf(acc_s[mt][nt][2 * h + e] - mn);
                        rs += p;
                        int col = wn * 16 + nt * 8 + 2 * q + e;
                        Ps[col * 132 + row] = f2tf32(p);
                    }
                }
                rs += __shfl_xor_sync(0xffffffffu, rs, 1);
                rs += __shfl_xor_sync(0xffffffffu, rs, 2);
                if (q == 0) red[wn * 128 + row] = rs;
            }
        }
#pragma unroll
        for (int mt = 0; mt < 2; mt++) {
#pragma unroll
            for (int h = 0; h < 2; h++) {
                int row = wm2 * 32 + mt * 16 + g + 8 * h;
                float a = al_s[row];
#pragma unroll
                for (int nt = 0; nt < 5; nt++) {
                    O[mt][nt][2 * h + 0] *= a;
                    O[mt][nt][2 * h + 1] *= a;
                }
            }
        }
        __syncthreads();
        if (tid < 128)
            l_s[tid] = l_s[tid] * al_s[tid] +
                       red[tid] + red[128 + tid] + red[256 + tid] + red[384 + tid];

#pragma unroll
        for (int ks = 0; ks < 64; ks += 8) {
            uint32_t af[2][4], bf[5][2];
#pragma unroll
            for (int mt = 0; mt < 2; mt++) {
                int mb = wm2 * 32 + mt * 16;
                af[mt][0] = Ps[(ks + q    ) * 132 + mb + g    ];
                af[mt][1] = Ps[(ks + q    ) * 132 + mb + g + 8];
                af[mt][2] = Ps[(ks + q + 4) * 132 + mb + g    ];
                af[mt][3] = Ps[(ks + q + 4) * 132 + mb + g + 8];
            }
#pragma unroll
            for (int nt = 0; nt < 5; nt++) {
                int nb = wn2 * 40 + nt * 8;
                bf[nt][0] = Vs[(ks + q    ) * 84 + nb + g];
                bf[nt][1] = Vs[(ks + q + 4) * 84 + nb + g];
            }
#pragma unroll
            for (int mt = 0; mt < 2; mt++)
#pragma unroll
                for (int nt = 0; nt < 5; nt++)
                    mma_tf32(O[mt][nt],
                             af[mt][0], af[mt][1], af[mt][2], af[mt][3],
                             bf[nt][0], bf[nt][1]);
        }
    }
    __syncthreads();

#pragma unroll
    for (int mt = 0; mt < 2; mt++) {
#pragma unroll
        for (int h = 0; h < 2; h++) {
            int r = wm2 * 32 + mt * 16 + g + 8 * h;
            if (q0 + r >= S) continue;
            float inv = 1.0f / l_s[r];
#pragma unroll
            for (int nt = 0; nt < 5; nt++) {
#pragma unroll
                for (int e = 0; e < 2; e++) {
                    int c = wn2 * 40 + nt * 8 + 2 * q + e;
                    if (c < HDIM)
                        attn[(size_t)(st + q0 + r) * DMODEL + head * HDIM + c] =
                            O[mt][nt][2 * h + e] * inv;
                }
            }
        }
    }
}

// ---------------------------------------------------------------------------
// Host launcher
// ---------------------------------------------------------------------------
#define SYM(p, s) do { void* _t; cudaGetSymbolAddress(&_t, s); p = (float*)_t; } while (0)

static inline dim3 ggrid2(int Md, int Nd) {
    return dim3((Nd + G2_BN - 1) / G2_BN, (Md + G2_BM - 1) / G2_BM);
}

extern "C" void kernel_launch(void* const* d_in, const int* in_sizes, int n_in,
                              void* d_out, int out_size)
{
    (void)in_sizes; (void)n_in; (void)out_size;
    const float* pixel    = (const float*)d_in[0];
    const float* patch_w  = (const float*)d_in[2];
    const float* patch_b  = (const float*)d_in[3];
    const float* pos_tab  = (const float*)d_in[4];
    const float* ln1_s    = (const float*)d_in[5];
    const float* ln1_b    = (const float*)d_in[6];
    const float* qkv_w    = (const float*)d_in[7];
    const float* qkv_b    = (const float*)d_in[8];
    const float* proj_w   = (const float*)d_in[9];
    const float* proj_b   = (const float*)d_in[10];
    const float* ln2_s    = (const float*)d_in[11];
    const float* ln2_b    = (const float*)d_in[12];
    const float* fc1_w    = (const float*)d_in[13];
    const float* fc1_b    = (const float*)d_in[14];
    const float* fc2_w    = (const float*)d_in[15];
    const float* fc2_b    = (const float*)d_in[16];
    const float* m_ln_s   = (const float*)d_in[17];
    const float* m_ln_b   = (const float*)d_in[18];
    const float* m_fc1_w  = (const float*)d_in[19];
    const float* m_fc1_b  = (const float*)d_in[20];
    const float* m_fc2_w  = (const float*)d_in[21];
    const float* m_fc2_b  = (const float*)d_in[22];
    float* out = (float*)d_out;

    float *x, *h, *qkv, *attn, *mlp;
    SYM(x, g_x); SYM(h, g_h); SYM(qkv, g_qkv); SYM(attn, g_attn);
    SYM(mlp, g_mlp);

    static bool attr_set = false;
    if (!attr_set) {
        cudaFuncSetAttribute(flash_attn,
                             cudaFuncAttributeMaxDynamicSharedMemorySize, FA_BYTES);
        cudaFuncSetAttribute(gemm_tc2<EPI_BIAS>,
                             cudaFuncAttributeMaxDynamicSharedMemorySize, G2_SMEM_BYTES);
        cudaFuncSetAttribute(gemm_tc2<EPI_BIAS_GELU>,
                             cudaFuncAttributeMaxDynamicSharedMemorySize, G2_SMEM_BYTES);
        cudaFuncSetAttribute(gemm_tc2<EPI_BIAS_RES>,
                             cudaFuncAttributeMaxDynamicSharedMemorySize, G2_SMEM_BYTES);
        attr_set = true;
    }

    cossin_kernel<<<(NTOK * 36 + 255) / 256, 256>>>();

    // Patch embed
    gemm_tc2<EPI_BIAS><<<ggrid2(NTOK, DMODEL), 256, G2_SMEM_BYTES>>>(
        pixel, 1536, patch_w, DMODEL, x, DMODEL,
        patch_b, nullptr, 0, NTOK, DMODEL, 1536);

    posadd_kernel<<<NTOK, 288>>>(pos_tab);

    for (int l = 0; l < 2; l++) {
        const float* l1s = ln1_s + l * DMODEL;
        const float* l1b = ln1_b + l * DMODEL;
        const float* qw  = qkv_w + (size_t)l * DMODEL * QKVW;
        const float* qb  = qkv_b + (size_t)l * QKVW;
        const float* pw  = proj_w + (size_t)l * DMODEL * DMODEL;
        const float* pb  = proj_b + (size_t)l * DMODEL;
        const float* l2s = ln2_s + l * DMODEL;
        const float* l2b = ln2_b + l * DMODEL;
        const float* f1w = fc1_w + (size_t)l * DMODEL * IDIM;
        const float* f1b = fc1_b + (size_t)l * IDIM;
        const float* f2w = fc2_w + (size_t)l * IDIM * DMODEL;
        const float* f2b = fc2_b + (size_t)l * DMODEL;

        ln_kernel<<<NTOK, 288>>>(x, h, l1s, l1b);

        gemm_tc2<EPI_BIAS><<<ggrid2(NTOK, QKVW), 256, G2_SMEM_BYTES>>>(
            h, DMODEL, qw, QKVW, qkv, QKVW,
            qb, nullptr, 0, NTOK, QKVW, DMODEL);

        rope_kernel<<<NTOK, 576>>>();

        flash_attn<<<dim3(50, HEADS), 256, FA_BYTES>>>(qkv, attn);

        gemm_tc2<EPI_BIAS_RES><<<ggrid2(NTOK, DMODEL), 256, G2_SMEM_BYTES>>>(
            attn, DMODEL, pw, DMODEL, x, DMODEL,
            pb, x, DMODEL, NTOK, DMODEL, DMODEL);

        ln_kernel<<<NTOK, 288>>>(x, h, l2s, l2b);

        gemm_tc2<EPI_BIAS_GELU><<<ggrid2(NTOK, IDIM), 256, G2_SMEM_BYTES>>>(
            h, DMODEL, f1w, IDIM, mlp, IDIM,
            f1b, nullptr, 0, NTOK, IDIM, DMODEL);

        gemm_tc2<EPI_BIAS_RES><<<ggrid2(NTOK, DMODEL), 256, G2_SMEM_BYTES>>>(
            mlp, IDIM, f2w, DMODEL, x, DMODEL,
            f2b, x, DMODEL, NTOK, DMODEL, IDIM);
    }

    // merger
    ln_kernel<<<NTOK, 288>>>(x, h, m_ln_s, m_ln_b);

    gemm_tc2<EPI_BIAS_GELU><<<ggrid2(MROWS, MD), 256, G2_SMEM_BYTES>>>(
        h, MD, m_fc1_w, MD, mlp, MD,
        m_fc1_b, nullptr, 0, MROWS, MD, MD);

    gemm_tc2<EPI_BIAS><<<ggrid2(MROWS, DOUT), 256, G2_SMEM_BYTES>>>(
        mlp, MD, m_fc2_w, DOUT, out, DOUT,
        m_fc2_b, nullptr, 0, MROWS, DOUT, MD);
}